// round 4
// baseline (speedup 1.0000x reference)
#include <cuda_runtime.h>
#include <cuda_bf16.h>
#include <math.h>
#include <stdint.h>

#define NN    100000
#define EE    1600000
#define CC    128
#define FIN   64
#define NSTEP 4
#define NEG_SLOPE 0.01f

// ---------------- scratch (static device globals) ----------------
__device__ __align__(256) float g_h  [(size_t)NN * CC];
__device__ __align__(256) float g_m  [(size_t)NN * CC];
__device__ __align__(256) float g_G  [(size_t)NN * 3 * CC];
__device__ __align__(256) float g_Hn [(size_t)NN * CC];
// bf16 hi/lo operand arrays
__device__ __align__(256) __nv_bfloat16 g_xh[(size_t)NN * FIN], g_xl[(size_t)NN * FIN];
__device__ __align__(256) __nv_bfloat16 g_hh[(size_t)NN * CC],  g_hl[(size_t)NN * CC];
__device__ __align__(256) __nv_bfloat16 g_ah[(size_t)NN * CC],  g_al[(size_t)NN * CC];
__device__ __align__(256) __nv_bfloat16 g_Bemb_h[CC * FIN],  g_Bemb_l[CC * FIN];
__device__ __align__(256) __nv_bfloat16 g_Bg_h[512 * 256],   g_Bg_l[512 * 256];
__device__ __align__(256) __nv_bfloat16 g_Bm_h[CC * CC],     g_Bm_l[CC * CC];
// CSR
__device__ int   g_deg[NN];
__device__ int   g_rowstart[NN + 1];
__device__ int   g_cursor[NN];
__device__ int   g_csrsrc[EE];
__device__ int   g_blocksum[128];
__device__ int   g_blockoff[128];
__device__ int   g_is64;
__device__ float g_colsum[CC];

// ---------------- helpers ----------------
__device__ __forceinline__ uint32_t smem_u32(const void* p) {
    uint32_t a;
    asm("{ .reg .u64 t; cvta.to.shared.u64 t, %1; cvt.u32.u64 %0, t; }" : "=r"(a) : "l"(p));
    return a;
}
__device__ __forceinline__ void cp16(uint32_t dst, const void* src, int sz) {
    asm volatile("cp.async.cg.shared.global [%0], [%1], 16, %2;"
                 :: "r"(dst), "l"(src), "r"(sz));
}
#define CP_COMMIT() asm volatile("cp.async.commit_group;" ::: "memory")
#define CP_WAIT0()  asm volatile("cp.async.wait_group 0;" ::: "memory")

__device__ __forceinline__ void mma_bf16(float* d, const uint32_t* a, const uint32_t* b) {
    asm volatile(
        "mma.sync.aligned.m16n8k16.row.col.f32.bf16.bf16.f32 "
        "{%0,%1,%2,%3}, {%4,%5,%6,%7}, {%8,%9}, {%0,%1,%2,%3};"
        : "+f"(d[0]), "+f"(d[1]), "+f"(d[2]), "+f"(d[3])
        : "r"(a[0]), "r"(a[1]), "r"(a[2]), "r"(a[3]), "r"(b[0]), "r"(b[1]));
}

__device__ __forceinline__ void split1(float v, __nv_bfloat16& hi, __nv_bfloat16& lo) {
    hi = __float2bfloat16(v);
    lo = __float2bfloat16(v - __bfloat162float(hi));
}

// ---------------- edge dtype detection ----------------
__global__ void detect_k(const void* __restrict__ edges) {
    if (threadIdx.x == 0 && blockIdx.x == 0) {
        const long long* p = (const long long*)edges;
        int is64 = 1;
        for (int i = 0; i < 256; i++) {
            long long v = p[i];
            if (v < 0 || v >= (long long)NN) { is64 = 0; break; }
        }
        g_is64 = is64;
    }
}
__device__ __forceinline__ int edge_at(const void* edges, int which, int e, bool is64) {
    if (is64) return (int)((const long long*)edges)[(size_t)which * EE + e];
    return ((const int*)edges)[(size_t)which * EE + e];
}

// ---------------- CSR build ----------------
__global__ void zero_deg_k() {
    for (int i = blockIdx.x * blockDim.x + threadIdx.x; i < NN; i += gridDim.x * blockDim.x)
        g_deg[i] = 0;
}
__global__ void hist_k(const void* __restrict__ edges) {
    bool is64 = g_is64;
    for (int e = blockIdx.x * blockDim.x + threadIdx.x; e < EE; e += gridDim.x * blockDim.x)
        atomicAdd(&g_deg[edge_at(edges, 1, e, is64)], 1);
}
__global__ void scan1_k() {
    __shared__ int s[1024];
    int tid = threadIdx.x;
    int i = blockIdx.x * 1024 + tid;
    int v = (i < NN) ? g_deg[i] : 0;
    s[tid] = v;
    __syncthreads();
    for (int off = 1; off < 1024; off <<= 1) {
        int t = (tid >= off) ? s[tid - off] : 0;
        __syncthreads();
        s[tid] += t;
        __syncthreads();
    }
    if (i < NN) g_rowstart[i] = s[tid] - v;
    if (tid == 1023) g_blocksum[blockIdx.x] = s[1023];
}
__global__ void scan2_k(int nb) {
    if (threadIdx.x == 0 && blockIdx.x == 0) {
        int acc = 0;
        for (int b = 0; b < nb; b++) { int t = g_blocksum[b]; g_blockoff[b] = acc; acc += t; }
        g_rowstart[NN] = acc;
    }
}
__global__ void scan3_k() {
    int i = blockIdx.x * 1024 + threadIdx.x;
    if (i < NN) {
        int v = g_rowstart[i] + g_blockoff[blockIdx.x];
        g_rowstart[i] = v;
        g_cursor[i] = v;
    }
}
__global__ void scatter_k(const void* __restrict__ edges) {
    bool is64 = g_is64;
    for (int e = blockIdx.x * blockDim.x + threadIdx.x; e < EE; e += gridDim.x * blockDim.x) {
        int src = edge_at(edges, 0, e, is64);
        int dst = edge_at(edges, 1, e, is64);
        g_csrsrc[atomicAdd(&g_cursor[dst], 1)] = src;
    }
}

// ---------------- operand conversion / weight packing ----------------
__global__ void convert_x_k(const float* __restrict__ x) {
    int i = blockIdx.x * blockDim.x + threadIdx.x;
    if (i >= NN * FIN) return;
    split1(x[i], g_xh[i], g_xl[i]);
}
__global__ void pack_emb_k(const float* __restrict__ Win) {   // B[n][k] = Win[n][k], 128x64
    int i = blockIdx.x * blockDim.x + threadIdx.x;
    if (i >= CC * FIN) return;
    split1(Win[i], g_Bemb_h[i], g_Bemb_l[i]);
}
__global__ void pack_gru_k(const float* __restrict__ Wih, const float* __restrict__ Whh) {
    int i = blockIdx.x * blockDim.x + threadIdx.x;   // 512*256
    if (i >= 512 * 256) return;
    int n = i >> 8, k = i & 255;
    float v;
    if (n < 384) v = (k < 128) ? Wih[n * 128 + k] : Whh[n * 128 + (k - 128)];
    else         v = (k < 128) ? 0.f : Whh[(256 + (n - 384)) * 128 + (k - 128)];
    split1(v, g_Bg_h[i], g_Bg_l[i]);
}
__global__ void pack_mpnn_k(const float* __restrict__ W) {    // B[n][k] = W[k][n], 128x128
    int i = blockIdx.x * blockDim.x + threadIdx.x;
    if (i >= CC * CC) return;
    int n = i >> 7, k = i & 127;
    split1(W[k * CC + n], g_Bm_h[i], g_Bm_l[i]);
}

// ---------------- pipelined bf16-split tensor-core NT GEMM ----------------
// C[M,N] = A[M,K]*B[N,K]^T with A = Ahi+Alo, B = Bhi+Blo (3-term product).
// BM=128, BN=128, BK=32, 2-stage cp.async pipeline, 8 warps (warp tile 64x32).
#define ST 20                       // smem words per 32-bf16 row (pad -> conflict-free frags)
#define STG_WORDS (4 * 128 * ST)    // AH, AL, BH, BL tiles per stage
#define GEMM_SMEM (2 * STG_WORDS * 4)

__global__ void __launch_bounds__(256, 2) tc_gemm(
    const __nv_bfloat16* __restrict__ Ah0, const __nv_bfloat16* __restrict__ Al0, int lda0,
    const __nv_bfloat16* __restrict__ Ah1, const __nv_bfloat16* __restrict__ Al1, int lda1, int KA0,
    const __nv_bfloat16* __restrict__ Bh,  const __nv_bfloat16* __restrict__ Bl,  int ldb,
    float* __restrict__ C0, int ldc0, int ycut,
    float* __restrict__ C1, int ldc1,
    __nv_bfloat16* __restrict__ Oh, __nv_bfloat16* __restrict__ Ol,
    int M, int Ktot)
{
    extern __shared__ uint32_t dsm[];
    const uint32_t sbase = smem_u32(dsm);

    const int tid  = threadIdx.x;
    const int lane = tid & 31;
    const int warp = tid >> 5;
    const int wr = warp & 1;          // 64-row strip
    const int wc = warp >> 1;         // 32-col strip
    const int g  = lane >> 2;
    const int t  = lane & 3;

    const int row0 = blockIdx.x * 128;
    const int col0 = blockIdx.y * 128;
    const int niter = Ktot >> 5;

    float acc[4][4][4];
#pragma unroll
    for (int i = 0; i < 4; i++)
#pragma unroll
        for (int j = 0; j < 4; j++)
#pragma unroll
            for (int k = 0; k < 4; k++) acc[i][j][k] = 0.f;

    // ---- producer lambda-ish: issue one stage's cp.asyncs ----
    auto load_stage = [&](int buf, int kt) {
        const uint32_t stg = sbase + (uint32_t)buf * STG_WORDS * 4;
#pragma unroll
        for (int it = 0; it < 8; ++it) {
            int idx = tid + it * 256;
            int arr = idx >> 9;          // 0=AH 1=AL 2=BH 3=BL
            int rem = idx & 511;
            int r   = rem >> 2;
            int c16 = rem & 3;
            int gk  = kt + c16 * 8;
            uint32_t dst = stg + (uint32_t)(arr * 128 * ST + r * ST + c16 * 4) * 4;
            const __nv_bfloat16* src;
            int sz = 16;
            if (arr < 2) {
                int grow = row0 + r;
                int srow = (grow < M) ? grow : 0;
                if (grow >= M) sz = 0;
                if (gk < KA0) src = (arr == 0 ? Ah0 : Al0) + (size_t)srow * lda0 + gk;
                else          src = (arr == 0 ? Ah1 : Al1) + (size_t)srow * lda1 + (gk - KA0);
            } else {
                int n = col0 + r;
                src = (arr == 2 ? Bh : Bl) + (size_t)n * ldb + gk;
            }
            cp16(dst, src, sz);
        }
    };

    load_stage(0, 0);
    CP_COMMIT();

    for (int ch = 0; ch < niter; ++ch) {
        CP_WAIT0();
        __syncthreads();
        if (ch + 1 < niter) {
            load_stage((ch + 1) & 1, (ch + 1) * 32);
            CP_COMMIT();
        }

        const uint32_t* S   = dsm + (ch & 1) * STG_WORDS;
        const uint32_t* sAH = S;
        const uint32_t* sAL = S + 128 * ST;
        const uint32_t* sBH = S + 2 * 128 * ST;
        const uint32_t* sBL = S + 3 * 128 * ST;

#pragma unroll
        for (int kk2 = 0; kk2 < 2; ++kk2) {       // two k16 chunks within BK=32
            const int kw = kk2 * 8;
            uint32_t bh[4][2], bl[4][2];
#pragma unroll
            for (int nt = 0; nt < 4; nt++) {
                int bo = (wc * 32 + nt * 8 + g) * ST + kw + t;
                bh[nt][0] = sBH[bo]; bh[nt][1] = sBH[bo + 4];
                bl[nt][0] = sBL[bo]; bl[nt][1] = sBL[bo + 4];
            }
#pragma unroll
            for (int mt = 0; mt < 4; mt++) {
                int ao = (wr * 64 + mt * 16 + g) * ST + kw + t;
                uint32_t ah[4] = { sAH[ao], sAH[ao + 8 * ST], sAH[ao + 4], sAH[ao + 8 * ST + 4] };
                uint32_t al[4] = { sAL[ao], sAL[ao + 8 * ST], sAL[ao + 4], sAL[ao + 8 * ST + 4] };
#pragma unroll
                for (int nt = 0; nt < 4; nt++) {
                    mma_bf16(acc[mt][nt], ah, bh[nt]);
                    mma_bf16(acc[mt][nt], ah, bl[nt]);
                    mma_bf16(acc[mt][nt], al, bh[nt]);
                }
            }
        }
        __syncthreads();
    }

    // ---- epilogue ----
    float* Cm; int ldc; int cb;
    if ((int)blockIdx.y < ycut) { Cm = C0; ldc = ldc0; cb = blockIdx.y * 128; }
    else                        { Cm = C1; ldc = ldc1; cb = (blockIdx.y - ycut) * 128; }

#pragma unroll
    for (int mt = 0; mt < 4; mt++) {
        int rbase = row0 + wr * 64 + mt * 16 + g;
#pragma unroll
        for (int nt = 0; nt < 4; nt++) {
            int col = cb + wc * 32 + nt * 8 + 2 * t;
            float v0 = acc[mt][nt][0], v1 = acc[mt][nt][1];
            float v2 = acc[mt][nt][2], v3 = acc[mt][nt][3];
            if (rbase < M) {
                *reinterpret_cast<float2*>(Cm + (size_t)rbase * ldc + col) = make_float2(v0, v1);
                if (Oh) {
                    __nv_bfloat16 h0, l0, h1, l1;
                    split1(v0, h0, l0); split1(v1, h1, l1);
                    __nv_bfloat162 hp; hp.x = h0; hp.y = h1;
                    __nv_bfloat162 lp; lp.x = l0; lp.y = l1;
                    *reinterpret_cast<__nv_bfloat162*>(Oh + (size_t)rbase * 128 + col) = hp;
                    *reinterpret_cast<__nv_bfloat162*>(Ol + (size_t)rbase * 128 + col) = lp;
                }
            }
            if (rbase + 8 < M) {
                *reinterpret_cast<float2*>(Cm + (size_t)(rbase + 8) * ldc + col) = make_float2(v2, v3);
                if (Oh) {
                    __nv_bfloat16 h0, l0, h1, l1;
                    split1(v2, h0, l0); split1(v3, h1, l1);
                    __nv_bfloat162 hp; hp.x = h0; hp.y = h1;
                    __nv_bfloat162 lp; lp.x = l0; lp.y = l1;
                    *reinterpret_cast<__nv_bfloat162*>(Oh + (size_t)(rbase + 8) * 128 + col) = hp;
                    *reinterpret_cast<__nv_bfloat162*>(Ol + (size_t)(rbase + 8) * 128 + col) = lp;
                }
            }
        }
    }
}

// ---------------- aggregation: agg = CSR-gather-sum of m, emitted as bf16 hi/lo ----------------
__global__ void aggregate_k() {
    int warp = (blockIdx.x * blockDim.x + threadIdx.x) >> 5;
    int lane = threadIdx.x & 31;
    if (warp >= NN) return;
    const float4* m4 = reinterpret_cast<const float4*>(g_m);
    int s = g_rowstart[warp], e = g_rowstart[warp + 1];
    float4 acc = make_float4(0.f, 0.f, 0.f, 0.f);
    int i = s;
    for (; i + 4 <= e; i += 4) {
        int s0 = g_csrsrc[i], s1 = g_csrsrc[i + 1], s2 = g_csrsrc[i + 2], s3 = g_csrsrc[i + 3];
        float4 v0 = m4[(size_t)s0 * 32 + lane];
        float4 v1 = m4[(size_t)s1 * 32 + lane];
        float4 v2 = m4[(size_t)s2 * 32 + lane];
        float4 v3 = m4[(size_t)s3 * 32 + lane];
        acc.x += (v0.x + v1.x) + (v2.x + v3.x);
        acc.y += (v0.y + v1.y) + (v2.y + v3.y);
        acc.z += (v0.z + v1.z) + (v2.z + v3.z);
        acc.w += (v0.w + v1.w) + (v2.w + v3.w);
    }
    for (; i < e; ++i) {
        float4 v = m4[(size_t)g_csrsrc[i] * 32 + lane];
        acc.x += v.x; acc.y += v.y; acc.z += v.z; acc.w += v.w;
    }
    __nv_bfloat16 h0, l0, h1, l1, h2, l2, h3, l3;
    split1(acc.x, h0, l0); split1(acc.y, h1, l1);
    split1(acc.z, h2, l2); split1(acc.w, h3, l3);
    size_t off = (size_t)warp * CC + lane * 4;
    __nv_bfloat162 hp0; hp0.x = h0; hp0.y = h1;
    __nv_bfloat162 hp1; hp1.x = h2; hp1.y = h3;
    __nv_bfloat162 lp0; lp0.x = l0; lp0.y = l1;
    __nv_bfloat162 lp1; lp1.x = l2; lp1.y = l3;
    *reinterpret_cast<__nv_bfloat162*>(g_ah + off)     = hp0;
    *reinterpret_cast<__nv_bfloat162*>(g_ah + off + 2) = hp1;
    *reinterpret_cast<__nv_bfloat162*>(g_al + off)     = lp0;
    *reinterpret_cast<__nv_bfloat162*>(g_al + off + 2) = lp1;
}

// ---------------- GRU gates; also emit h in bf16 hi/lo ----------------
__global__ void gate_k(const float* __restrict__ bih, const float* __restrict__ bhh) {
    int idx = blockIdx.x * blockDim.x + threadIdx.x;
    if (idx >= NN * CC) return;
    int c = idx & (CC - 1);
    size_t n = (size_t)(idx >> 7);
    const float* Gp = g_G + n * (3 * CC);
    float Gr = Gp[c], Gz = Gp[CC + c], Gn = Gp[2 * CC + c];
    float Hnv = g_Hn[n * CC + c];
    float r = 1.f / (1.f + expf(-(Gr + bih[c] + bhh[c])));
    float z = 1.f / (1.f + expf(-(Gz + bih[CC + c] + bhh[CC + c])));
    float nn = tanhf((Gn - Hnv) + bih[2 * CC + c] + r * (Hnv + bhh[2 * CC + c]));
    float h = g_h[idx];
    float hnew = (1.f - z) * nn + z * h;
    g_h[idx] = hnew;
    split1(hnew, g_hh[idx], g_hl[idx]);
}

// ---------------- readout ----------------
__global__ void zero_colsum_k() { if (threadIdx.x < CC) g_colsum[threadIdx.x] = 0.f; }

__global__ void reduce_cols_k() {
    int c = threadIdx.x;
    float acc = 0.f;
    for (int n = blockIdx.x; n < NN; n += gridDim.x) {
        float v = g_h[(size_t)n * CC + c];
        acc += (v >= 0.f) ? v : NEG_SLOPE * v;
    }
    atomicAdd(&g_colsum[c], acc);
}

__global__ void finalize_k(const float* __restrict__ wpred, const float* __restrict__ bpred,
                           float* __restrict__ out) {
    int lane = threadIdx.x;
    float s = 0.f;
    for (int c = lane; c < CC; c += 32) s += g_colsum[c] * wpred[c];
    for (int o = 16; o; o >>= 1) s += __shfl_xor_sync(0xFFFFFFFFu, s, o);
    if (lane == 0) out[0] = s * (1.0f / (float)NN) + bpred[0];
}

// ---------------- launch ----------------
extern "C" void kernel_launch(void* const* d_in, const int* in_sizes, int n_in,
                              void* d_out, int out_size) {
    const float* x      = (const float*)d_in[0];
    const void*  edges  = d_in[1];
    const float* W_in   = (const float*)d_in[2];
    const float* W_mpnn = (const float*)d_in[3];
    const float* W_ih   = (const float*)d_in[4];
    const float* W_hh   = (const float*)d_in[5];
    const float* b_ih   = (const float*)d_in[6];
    const float* b_hh   = (const float*)d_in[7];
    const float* W_pred = (const float*)d_in[8];
    const float* b_pred = (const float*)d_in[9];
    float* out = (float*)d_out;

    // resolve device-global addresses
    void *p_h, *p_m, *p_G, *p_Hn, *p_xh, *p_xl, *p_hh, *p_hl, *p_ah, *p_al;
    void *p_Beh, *p_Bel, *p_Bgh, *p_Bgl, *p_Bmh, *p_Bml;
    cudaGetSymbolAddress(&p_h,   g_h);
    cudaGetSymbolAddress(&p_m,   g_m);
    cudaGetSymbolAddress(&p_G,   g_G);
    cudaGetSymbolAddress(&p_Hn,  g_Hn);
    cudaGetSymbolAddress(&p_xh,  g_xh);
    cudaGetSymbolAddress(&p_xl,  g_xl);
    cudaGetSymbolAddress(&p_hh,  g_hh);
    cudaGetSymbolAddress(&p_hl,  g_hl);
    cudaGetSymbolAddress(&p_ah,  g_ah);
    cudaGetSymbolAddress(&p_al,  g_al);
    cudaGetSymbolAddress(&p_Beh, g_Bemb_h);
    cudaGetSymbolAddress(&p_Bel, g_Bemb_l);
    cudaGetSymbolAddress(&p_Bgh, g_Bg_h);
    cudaGetSymbolAddress(&p_Bgl, g_Bg_l);
    cudaGetSymbolAddress(&p_Bmh, g_Bm_h);
    cudaGetSymbolAddress(&p_Bml, g_Bm_l);
    float* h_  = (float*)p_h;
    float* m_  = (float*)p_m;
    float* G_  = (float*)p_G;
    float* Hn_ = (float*)p_Hn;
    __nv_bfloat16 *xh = (__nv_bfloat16*)p_xh, *xl = (__nv_bfloat16*)p_xl;
    __nv_bfloat16 *hh = (__nv_bfloat16*)p_hh, *hl = (__nv_bfloat16*)p_hl;
    __nv_bfloat16 *ah = (__nv_bfloat16*)p_ah, *al = (__nv_bfloat16*)p_al;
    __nv_bfloat16 *Beh = (__nv_bfloat16*)p_Beh, *Bel = (__nv_bfloat16*)p_Bel;
    __nv_bfloat16 *Bgh = (__nv_bfloat16*)p_Bgh, *Bgl = (__nv_bfloat16*)p_Bgl;
    __nv_bfloat16 *Bmh = (__nv_bfloat16*)p_Bmh, *Bml = (__nv_bfloat16*)p_Bml;

    cudaFuncSetAttribute(tc_gemm, cudaFuncAttributeMaxDynamicSharedMemorySize, GEMM_SMEM);

    const int NB = (NN + 1023) / 1024;

    // CSR build
    detect_k<<<1, 32>>>(edges);
    zero_deg_k<<<128, 256>>>();
    hist_k<<<512, 256>>>(edges);
    scan1_k<<<NB, 1024>>>();
    scan2_k<<<1, 32>>>(NB);
    scan3_k<<<NB, 1024>>>();
    scatter_k<<<512, 256>>>(edges);

    // operand prep
    convert_x_k<<<(NN * FIN + 255) / 256, 256>>>(x);
    pack_emb_k<<<(CC * FIN + 255) / 256, 256>>>(W_in);
    pack_gru_k<<<(512 * 256 + 255) / 256, 256>>>(W_ih, W_hh);

    dim3 grid1((NN + 127) / 128, 1);
    dim3 grid4((NN + 127) / 128, 4);

    // h = x @ W_in^T  (K=64, N=128): fp32 h + bf16 hi/lo
    tc_gemm<<<grid1, 256, GEMM_SMEM>>>(xh, xl, FIN, xh, xl, FIN, FIN,
                                       Beh, Bel, FIN,
                                       h_, CC, 1, h_, CC,
                                       hh, hl, NN, FIN);

    for (int step = 0; step < NSTEP; ++step) {
        // m = h @ W_mpnn[step]
        pack_mpnn_k<<<(CC * CC + 255) / 256, 256>>>(W_mpnn + (size_t)step * CC * CC);
        tc_gemm<<<grid1, 256, GEMM_SMEM>>>(hh, hl, CC, hh, hl, CC, CC,
                                           Bmh, Bml, CC,
                                           m_, CC, 1, m_, CC,
                                           (__nv_bfloat16*)0, (__nv_bfloat16*)0, NN, CC);

        // agg (bf16 hi/lo) via CSR gather
        aggregate_k<<<NN / 8, 256>>>();

        // [G | Hn] = [agg | h] @ [Wih|Whh ; 0|Whh_n]^T  (K=256, N=512)
        tc_gemm<<<grid4, 256, GEMM_SMEM>>>(ah, al, CC, hh, hl, CC, CC,
                                           Bgh, Bgl, 2 * CC,
                                           G_, 3 * CC, 3, Hn_, CC,
                                           (__nv_bfloat16*)0, (__nv_bfloat16*)0, NN, 2 * CC);

        gate_k<<<(NN * CC) / 256, 256>>>(b_ih, b_hh);
    }

    zero_colsum_k<<<1, 128>>>();
    reduce_cols_k<<<2048, 128>>>();
    finalize_k<<<1, 32>>>(W_pred, b_pred, out);
}

// round 5
// speedup vs baseline: 1.0469x; 1.0469x over previous
#include <cuda_runtime.h>
#include <cuda_bf16.h>
#include <math.h>
#include <stdint.h>

#define NN    100000
#define EE    1600000
#define CC    128
#define FIN   64
#define NSTEP 4
#define NEG_SLOPE 0.01f

// ---------------- scratch (static device globals) ----------------
// ping-pong hidden state
__device__ __align__(256) float g_h0[(size_t)NN * CC], g_h1[(size_t)NN * CC];
__device__ __align__(256) __nv_bfloat16 g_hh0[(size_t)NN * CC], g_hl0[(size_t)NN * CC];
__device__ __align__(256) __nv_bfloat16 g_hh1[(size_t)NN * CC], g_hl1[(size_t)NN * CC];
// aggregated h (bf16 hi/lo)
__device__ __align__(256) __nv_bfloat16 g_ah[(size_t)NN * CC], g_al[(size_t)NN * CC];
// x in bf16 hi/lo
__device__ __align__(256) __nv_bfloat16 g_xh[(size_t)NN * FIN], g_xl[(size_t)NN * FIN];
// weights
__device__ __align__(256) __nv_bfloat16 g_Bemb_h[CC * FIN], g_Bemb_l[CC * FIN];
__device__ __align__(256) float g_W1[NSTEP][384 * 128];            // Wm @ Wih^T per step
__device__ __align__(256) __nv_bfloat16 g_Bg_h[NSTEP][512 * 256];  // fused+reordered GRU B
__device__ __align__(256) __nv_bfloat16 g_Bg_l[NSTEP][512 * 256];
// CSR
__device__ int   g_deg[NN];
__device__ int   g_rowstart[NN + 1];
__device__ int   g_cursor[NN];
__device__ int   g_csrsrc[EE];
__device__ int   g_blocksum[128];
__device__ int   g_blockoff[128];
__device__ int   g_is64;
__device__ float g_colsum[CC];

// ---------------- helpers ----------------
__device__ __forceinline__ uint32_t smem_u32(const void* p) {
    uint32_t a;
    asm("{ .reg .u64 t; cvta.to.shared.u64 t, %1; cvt.u32.u64 %0, t; }" : "=r"(a) : "l"(p));
    return a;
}
__device__ __forceinline__ void cp16(uint32_t dst, const void* src, int sz) {
    asm volatile("cp.async.cg.shared.global [%0], [%1], 16, %2;"
                 :: "r"(dst), "l"(src), "r"(sz));
}
#define CP_COMMIT() asm volatile("cp.async.commit_group;" ::: "memory")
#define CP_WAIT0()  asm volatile("cp.async.wait_group 0;" ::: "memory")

__device__ __forceinline__ void mma_bf16(float* d, const uint32_t* a, const uint32_t* b) {
    asm volatile(
        "mma.sync.aligned.m16n8k16.row.col.f32.bf16.bf16.f32 "
        "{%0,%1,%2,%3}, {%4,%5,%6,%7}, {%8,%9}, {%0,%1,%2,%3};"
        : "+f"(d[0]), "+f"(d[1]), "+f"(d[2]), "+f"(d[3])
        : "r"(a[0]), "r"(a[1]), "r"(a[2]), "r"(a[3]), "r"(b[0]), "r"(b[1]));
}
__device__ __forceinline__ void split1(float v, __nv_bfloat16& hi, __nv_bfloat16& lo) {
    hi = __float2bfloat16(v);
    lo = __float2bfloat16(v - __bfloat162float(hi));
}

// ---------------- edge dtype detection ----------------
__global__ void detect_k(const void* __restrict__ edges) {
    if (threadIdx.x == 0 && blockIdx.x == 0) {
        const long long* p = (const long long*)edges;
        int is64 = 1;
        for (int i = 0; i < 256; i++) {
            long long v = p[i];
            if (v < 0 || v >= (long long)NN) { is64 = 0; break; }
        }
        g_is64 = is64;
    }
}
__device__ __forceinline__ int edge_at(const void* edges, int which, int e, bool is64) {
    if (is64) return (int)((const long long*)edges)[(size_t)which * EE + e];
    return ((const int*)edges)[(size_t)which * EE + e];
}

// ---------------- CSR build ----------------
__global__ void zero_deg_k() {
    for (int i = blockIdx.x * blockDim.x + threadIdx.x; i < NN; i += gridDim.x * blockDim.x)
        g_deg[i] = 0;
}
__global__ void hist_k(const void* __restrict__ edges) {
    bool is64 = g_is64;
    for (int e = blockIdx.x * blockDim.x + threadIdx.x; e < EE; e += gridDim.x * blockDim.x)
        atomicAdd(&g_deg[edge_at(edges, 1, e, is64)], 1);
}
__global__ void scan1_k() {
    __shared__ int s[1024];
    int tid = threadIdx.x;
    int i = blockIdx.x * 1024 + tid;
    int v = (i < NN) ? g_deg[i] : 0;
    s[tid] = v;
    __syncthreads();
    for (int off = 1; off < 1024; off <<= 1) {
        int t = (tid >= off) ? s[tid - off] : 0;
        __syncthreads();
        s[tid] += t;
        __syncthreads();
    }
    if (i < NN) g_rowstart[i] = s[tid] - v;
    if (tid == 1023) g_blocksum[blockIdx.x] = s[1023];
}
__global__ void scan2_k(int nb) {
    if (threadIdx.x == 0 && blockIdx.x == 0) {
        int acc = 0;
        for (int b = 0; b < nb; b++) { int t = g_blocksum[b]; g_blockoff[b] = acc; acc += t; }
        g_rowstart[NN] = acc;
    }
}
__global__ void scan3_k() {
    int i = blockIdx.x * 1024 + threadIdx.x;
    if (i < NN) {
        int v = g_rowstart[i] + g_blockoff[blockIdx.x];
        g_rowstart[i] = v;
        g_cursor[i] = v;
    }
}
__global__ void scatter_k(const void* __restrict__ edges) {
    bool is64 = g_is64;
    for (int e = blockIdx.x * blockDim.x + threadIdx.x; e < EE; e += gridDim.x * blockDim.x) {
        int src = edge_at(edges, 0, e, is64);
        int dst = edge_at(edges, 1, e, is64);
        g_csrsrc[atomicAdd(&g_cursor[dst], 1)] = src;
    }
}

// ---------------- operand / weight prep ----------------
__global__ void convert_x_k(const float* __restrict__ x) {
    int i = blockIdx.x * blockDim.x + threadIdx.x;
    if (i >= NN * FIN) return;
    split1(x[i], g_xh[i], g_xl[i]);
}
__global__ void pack_emb_k(const float* __restrict__ Win) {
    int i = blockIdx.x * blockDim.x + threadIdx.x;
    if (i >= CC * FIN) return;
    split1(Win[i], g_Bemb_h[i], g_Bemb_l[i]);
}
// W1[n][k] = sum_j Wm[k][j] * Wih[n][j]   (384x128, K=128)
__global__ void w1_k(const float* __restrict__ Wm, const float* __restrict__ Wih, int step) {
    int i = blockIdx.x * blockDim.x + threadIdx.x;
    if (i >= 384 * 128) return;
    int n = i >> 7, k = i & 127;
    const float* wm = Wm + k * 128;
    const float* wi = Wih + n * 128;
    float s = 0.f;
#pragma unroll 8
    for (int j = 0; j < 128; ++j) s = fmaf(wm[j], wi[j], s);
    g_W1[step][i] = s;
}
// Fused GRU B, reordered: row n' -> (y=n'>>7, gate=(n'>>5)&3, cl=n'&31, channel c=y*32+cl)
// gates 0..2: [W1 | Whh] logical row g*128+c ; gate 3 (hn): [0 | Whh row 256+c]
__global__ void pack_gru_k(const float* __restrict__ Whh, int step) {
    int i = blockIdx.x * blockDim.x + threadIdx.x;
    if (i >= 512 * 256) return;
    int np = i >> 8, k = i & 255;
    int y = np >> 7, gate = (np >> 5) & 3, cl = np & 31;
    int c = y * 32 + cl;
    float v;
    if (gate < 3) {
        int lr = gate * 128 + c;
        v = (k < 128) ? g_W1[step][lr * 128 + k] : Whh[lr * 128 + (k - 128)];
    } else {
        v = (k < 128) ? 0.f : Whh[(256 + c) * 128 + (k - 128)];
    }
    split1(v, g_Bg_h[step][i], g_Bg_l[step][i]);
}

// ---------------- shared gemm config ----------------
#define ST 20
#define STG_WORDS (4 * 128 * ST)
#define GEMM_SMEM (2 * STG_WORDS * 4)   // 80 KB (>= 128*132*4 epilogue stage)

// ---------------- embed gemm: h0 = x @ Win^T (K=64), writes fp32 + bf16 hi/lo ----------------
__global__ void __launch_bounds__(256, 2) tc_gemm_embed(
    const __nv_bfloat16* __restrict__ Ah, const __nv_bfloat16* __restrict__ Al,
    const __nv_bfloat16* __restrict__ Bh, const __nv_bfloat16* __restrict__ Bl,
    float* __restrict__ C, __nv_bfloat16* __restrict__ Oh, __nv_bfloat16* __restrict__ Ol,
    int M)
{
    extern __shared__ uint32_t dsm[];
    const uint32_t sbase = smem_u32(dsm);
    const int tid = threadIdx.x, lane = tid & 31, warp = tid >> 5;
    const int wr = warp & 1, wc = warp >> 1, g = lane >> 2, t = lane & 3;
    const int row0 = blockIdx.x * 128;

    float acc[4][4][4];
#pragma unroll
    for (int i = 0; i < 4; i++)
#pragma unroll
        for (int j = 0; j < 4; j++)
#pragma unroll
            for (int k = 0; k < 4; k++) acc[i][j][k] = 0.f;

    auto load_stage = [&](int buf, int kt) {
        const uint32_t stg = sbase + (uint32_t)buf * STG_WORDS * 4;
#pragma unroll
        for (int it = 0; it < 8; ++it) {
            int idx = tid + it * 256;
            int arr = idx >> 9, rem = idx & 511;
            int r = rem >> 2, c16 = rem & 3;
            int gk = kt + c16 * 8;
            uint32_t dst = stg + (uint32_t)(arr * 128 * ST + r * ST + c16 * 4) * 4;
            const __nv_bfloat16* src;
            int sz = 16;
            if (arr < 2) {
                int grow = row0 + r;
                int srow = (grow < M) ? grow : 0;
                if (grow >= M) sz = 0;
                src = (arr == 0 ? Ah : Al) + (size_t)srow * FIN + gk;
            } else {
                src = (arr == 2 ? Bh : Bl) + (size_t)r * FIN + gk;
            }
            cp16(dst, src, sz);
        }
    };

    load_stage(0, 0);
    CP_COMMIT();
    for (int ch = 0; ch < 2; ++ch) {           // K=64, BK=32
        CP_WAIT0();
        __syncthreads();
        if (ch == 0) { load_stage(1, 32); CP_COMMIT(); }
        const uint32_t* S = dsm + ch * STG_WORDS;
        const uint32_t *sAH = S, *sAL = S + 128 * ST, *sBH = S + 2 * 128 * ST, *sBL = S + 3 * 128 * ST;
#pragma unroll
        for (int kk2 = 0; kk2 < 2; ++kk2) {
            const int kw = kk2 * 8;
            uint32_t bh[4][2], bl[4][2];
#pragma unroll
            for (int nt = 0; nt < 4; nt++) {
                int bo = (wc * 32 + nt * 8 + g) * ST + kw + t;
                bh[nt][0] = sBH[bo]; bh[nt][1] = sBH[bo + 4];
                bl[nt][0] = sBL[bo]; bl[nt][1] = sBL[bo + 4];
            }
#pragma unroll
            for (int mt = 0; mt < 4; mt++) {
                int ao = (wr * 64 + mt * 16 + g) * ST + kw + t;
                uint32_t ah[4] = { sAH[ao], sAH[ao + 8 * ST], sAH[ao + 4], sAH[ao + 8 * ST + 4] };
                uint32_t al[4] = { sAL[ao], sAL[ao + 8 * ST], sAL[ao + 4], sAL[ao + 8 * ST + 4] };
#pragma unroll
                for (int nt = 0; nt < 4; nt++) {
                    mma_bf16(acc[mt][nt], ah, bh[nt]);
                    mma_bf16(acc[mt][nt], ah, bl[nt]);
                    mma_bf16(acc[mt][nt], al, bh[nt]);
                }
            }
        }
        __syncthreads();
    }

#pragma unroll
    for (int mt = 0; mt < 4; mt++) {
        int rbase = row0 + wr * 64 + mt * 16 + g;
#pragma unroll
        for (int nt = 0; nt < 4; nt++) {
            int col = wc * 32 + nt * 8 + 2 * t;
#pragma unroll
            for (int half = 0; half < 2; ++half) {
                int rr = rbase + half * 8;
                if (rr >= M) continue;
                float v0 = acc[mt][nt][half * 2], v1 = acc[mt][nt][half * 2 + 1];
                *reinterpret_cast<float2*>(C + (size_t)rr * CC + col) = make_float2(v0, v1);
                __nv_bfloat16 h0, l0, h1, l1;
                split1(v0, h0, l0); split1(v1, h1, l1);
                __nv_bfloat162 hp; hp.x = h0; hp.y = h1;
                __nv_bfloat162 lp; lp.x = l0; lp.y = l1;
                *reinterpret_cast<__nv_bfloat162*>(Oh + (size_t)rr * CC + col) = hp;
                *reinterpret_cast<__nv_bfloat162*>(Ol + (size_t)rr * CC + col) = lp;
            }
        }
    }
}

// ---------------- GRU gemm with fused gate epilogue ----------------
// A = [agg | h_in] (K=256, bf16 hi/lo), B = fused reordered (512x256).
// CTA (x,y): rows [128x,128x+128), channels [32y, 32y+32); tile cols = gate*32+cl.
__global__ void __launch_bounds__(256, 2) tc_gemm_gru(
    const __nv_bfloat16* __restrict__ Aah, const __nv_bfloat16* __restrict__ Aal,
    const __nv_bfloat16* __restrict__ Ahh, const __nv_bfloat16* __restrict__ Ahl,
    const __nv_bfloat16* __restrict__ Bh,  const __nv_bfloat16* __restrict__ Bl,
    const float* __restrict__ h_in, float* __restrict__ h_out,
    __nv_bfloat16* __restrict__ hh_out, __nv_bfloat16* __restrict__ hl_out,
    const float* __restrict__ bih, const float* __restrict__ bhh,
    int M)
{
    extern __shared__ uint32_t dsm[];
    const uint32_t sbase = smem_u32(dsm);
    const int tid = threadIdx.x, lane = tid & 31, warp = tid >> 5;
    const int wr = warp & 1, wc = warp >> 1, g = lane >> 2, t = lane & 3;
    const int row0 = blockIdx.x * 128;
    const int col0 = blockIdx.y * 128;

    float acc[4][4][4];
#pragma unroll
    for (int i = 0; i < 4; i++)
#pragma unroll
        for (int j = 0; j < 4; j++)
#pragma unroll
            for (int k = 0; k < 4; k++) acc[i][j][k] = 0.f;

    auto load_stage = [&](int buf, int kt) {
        const uint32_t stg = sbase + (uint32_t)buf * STG_WORDS * 4;
#pragma unroll
        for (int it = 0; it < 8; ++it) {
            int idx = tid + it * 256;
            int arr = idx >> 9, rem = idx & 511;
            int r = rem >> 2, c16 = rem & 3;
            int gk = kt + c16 * 8;
            uint32_t dst = stg + (uint32_t)(arr * 128 * ST + r * ST + c16 * 4) * 4;
            const __nv_bfloat16* src;
            int sz = 16;
            if (arr < 2) {
                int grow = row0 + r;
                int srow = (grow < M) ? grow : 0;
                if (grow >= M) sz = 0;
                if (gk < 128) src = (arr == 0 ? Aah : Aal) + (size_t)srow * CC + gk;
                else          src = (arr == 0 ? Ahh : Ahl) + (size_t)srow * CC + (gk - 128);
            } else {
                src = (arr == 2 ? Bh : Bl) + (size_t)(col0 + r) * 256 + gk;
            }
            cp16(dst, src, sz);
        }
    };

    load_stage(0, 0);
    CP_COMMIT();
    for (int ch = 0; ch < 8; ++ch) {            // K=256, BK=32
        CP_WAIT0();
        __syncthreads();
        if (ch + 1 < 8) { load_stage((ch + 1) & 1, (ch + 1) * 32); CP_COMMIT(); }
        const uint32_t* S = dsm + (ch & 1) * STG_WORDS;
        const uint32_t *sAH = S, *sAL = S + 128 * ST, *sBH = S + 2 * 128 * ST, *sBL = S + 3 * 128 * ST;
#pragma unroll
        for (int kk2 = 0; kk2 < 2; ++kk2) {
            const int kw = kk2 * 8;
            uint32_t bh[4][2], bl[4][2];
#pragma unroll
            for (int nt = 0; nt < 4; nt++) {
                int bo = (wc * 32 + nt * 8 + g) * ST + kw + t;
                bh[nt][0] = sBH[bo]; bh[nt][1] = sBH[bo + 4];
                bl[nt][0] = sBL[bo]; bl[nt][1] = sBL[bo + 4];
            }
#pragma unroll
            for (int mt = 0; mt < 4; mt++) {
                int ao = (wr * 64 + mt * 16 + g) * ST + kw + t;
                uint32_t ah[4] = { sAH[ao], sAH[ao + 8 * ST], sAH[ao + 4], sAH[ao + 8 * ST + 4] };
                uint32_t al[4] = { sAL[ao], sAL[ao + 8 * ST], sAL[ao + 4], sAL[ao + 8 * ST + 4] };
#pragma unroll
                for (int nt = 0; nt < 4; nt++) {
                    mma_bf16(acc[mt][nt], ah, bh[nt]);
                    mma_bf16(acc[mt][nt], ah, bl[nt]);
                    mma_bf16(acc[mt][nt], al, bh[nt]);
                }
            }
        }
        __syncthreads();
    }

    // ---- stage C tile into smem (reuses pipeline smem; all operand reads done) ----
    float* stage = reinterpret_cast<float*>(dsm);
#pragma unroll
    for (int mt = 0; mt < 4; mt++) {
        int r0 = wr * 64 + mt * 16 + g;
#pragma unroll
        for (int nt = 0; nt < 4; nt++) {
            int col = wc * 32 + nt * 8 + 2 * t;
            *reinterpret_cast<float2*>(&stage[r0 * 132 + col]) =
                make_float2(acc[mt][nt][0], acc[mt][nt][1]);
            *reinterpret_cast<float2*>(&stage[(r0 + 8) * 132 + col]) =
                make_float2(acc[mt][nt][2], acc[mt][nt][3]);
        }
    }
    __syncthreads();

    // ---- fused GRU gates: cols {0..31}=r, {32..63}=z, {64..95}=n, {96..127}=Hn ----
    const int y = blockIdx.y;
#pragma unroll
    for (int it = 0; it < 16; ++it) {
        int idx = tid + it * 256;           // 0..4095
        int row = idx >> 5, cl = idx & 31;
        int grow = row0 + row;
        if (grow >= M) continue;
        int c = y * 32 + cl;
        const float* sr = &stage[row * 132];
        float Gr = sr[cl], Gz = sr[32 + cl], Gn = sr[64 + cl], Hn = sr[96 + cl];
        float ho = h_in[(size_t)grow * CC + c];
        float r = 1.f / (1.f + expf(-(Gr + bih[c] + bhh[c])));
        float z = 1.f / (1.f + expf(-(Gz + bih[CC + c] + bhh[CC + c])));
        float nn = tanhf((Gn - Hn) + bih[2 * CC + c] + r * (Hn + bhh[2 * CC + c]));
        float hnew = (1.f - z) * nn + z * ho;
        h_out[(size_t)grow * CC + c] = hnew;
        __nv_bfloat16 hi, lo;
        split1(hnew, hi, lo);
        hh_out[(size_t)grow * CC + c] = hi;
        hl_out[(size_t)grow * CC + c] = lo;
    }
}

// ---------------- aggregation: agg = CSR-gather-sum of h_in, emit bf16 hi/lo ----------------
__global__ void aggregate_k(const float* __restrict__ h_in) {
    int warp = (blockIdx.x * blockDim.x + threadIdx.x) >> 5;
    int lane = threadIdx.x & 31;
    if (warp >= NN) return;
    const float4* m4 = reinterpret_cast<const float4*>(h_in);
    int s = g_rowstart[warp], e = g_rowstart[warp + 1];
    float4 acc = make_float4(0.f, 0.f, 0.f, 0.f);
    int i = s;
    for (; i + 4 <= e; i += 4) {
        int s0 = g_csrsrc[i], s1 = g_csrsrc[i + 1], s2 = g_csrsrc[i + 2], s3 = g_csrsrc[i + 3];
        float4 v0 = m4[(size_t)s0 * 32 + lane];
        float4 v1 = m4[(size_t)s1 * 32 + lane];
        float4 v2 = m4[(size_t)s2 * 32 + lane];
        float4 v3 = m4[(size_t)s3 * 32 + lane];
        acc.x += (v0.x + v1.x) + (v2.x + v3.x);
        acc.y += (v0.y + v1.y) + (v2.y + v3.y);
        acc.z += (v0.z + v1.z) + (v2.z + v3.z);
        acc.w += (v0.w + v1.w) + (v2.w + v3.w);
    }
    for (; i < e; ++i) {
        float4 v = m4[(size_t)g_csrsrc[i] * 32 + lane];
        acc.x += v.x; acc.y += v.y; acc.z += v.z; acc.w += v.w;
    }
    __nv_bfloat16 h0, l0, h1, l1, h2, l2, h3, l3;
    split1(acc.x, h0, l0); split1(acc.y, h1, l1);
    split1(acc.z, h2, l2); split1(acc.w, h3, l3);
    size_t off = (size_t)warp * CC + lane * 4;
    __nv_bfloat162 hp0; hp0.x = h0; hp0.y = h1;
    __nv_bfloat162 hp1; hp1.x = h2; hp1.y = h3;
    __nv_bfloat162 lp0; lp0.x = l0; lp0.y = l1;
    __nv_bfloat162 lp1; lp1.x = l2; lp1.y = l3;
    *reinterpret_cast<__nv_bfloat162*>(g_ah + off)     = hp0;
    *reinterpret_cast<__nv_bfloat162*>(g_ah + off + 2) = hp1;
    *reinterpret_cast<__nv_bfloat162*>(g_al + off)     = lp0;
    *reinterpret_cast<__nv_bfloat162*>(g_al + off + 2) = lp1;
}

// ---------------- readout ----------------
__global__ void zero_colsum_k() { if (threadIdx.x < CC) g_colsum[threadIdx.x] = 0.f; }

__global__ void reduce_cols_k(const float* __restrict__ h) {
    int c = threadIdx.x;
    float acc = 0.f;
    for (int n = blockIdx.x; n < NN; n += gridDim.x) {
        float v = h[(size_t)n * CC + c];
        acc += (v >= 0.f) ? v : NEG_SLOPE * v;
    }
    atomicAdd(&g_colsum[c], acc);
}

__global__ void finalize_k(const float* __restrict__ wpred, const float* __restrict__ bpred,
                           float* __restrict__ out) {
    int lane = threadIdx.x;
    float s = 0.f;
    for (int c = lane; c < CC; c += 32) s += g_colsum[c] * wpred[c];
    for (int o = 16; o; o >>= 1) s += __shfl_xor_sync(0xFFFFFFFFu, s, o);
    if (lane == 0) out[0] = s * (1.0f / (float)NN) + bpred[0];
}

// ---------------- launch ----------------
extern "C" void kernel_launch(void* const* d_in, const int* in_sizes, int n_in,
                              void* d_out, int out_size) {
    const float* x      = (const float*)d_in[0];
    const void*  edges  = d_in[1];
    const float* W_in   = (const float*)d_in[2];
    const float* W_mpnn = (const float*)d_in[3];
    const float* W_ih   = (const float*)d_in[4];
    const float* W_hh   = (const float*)d_in[5];
    const float* b_ih   = (const float*)d_in[6];
    const float* b_hh   = (const float*)d_in[7];
    const float* W_pred = (const float*)d_in[8];
    const float* b_pred = (const float*)d_in[9];
    float* out = (float*)d_out;

    void *p_h0, *p_h1, *p_hh0, *p_hl0, *p_hh1, *p_hl1, *p_ah, *p_al;
    void *p_xh, *p_xl, *p_Beh, *p_Bel, *p_Bgh, *p_Bgl;
    cudaGetSymbolAddress(&p_h0, g_h0);   cudaGetSymbolAddress(&p_h1, g_h1);
    cudaGetSymbolAddress(&p_hh0, g_hh0); cudaGetSymbolAddress(&p_hl0, g_hl0);
    cudaGetSymbolAddress(&p_hh1, g_hh1); cudaGetSymbolAddress(&p_hl1, g_hl1);
    cudaGetSymbolAddress(&p_ah, g_ah);   cudaGetSymbolAddress(&p_al, g_al);
    cudaGetSymbolAddress(&p_xh, g_xh);   cudaGetSymbolAddress(&p_xl, g_xl);
    cudaGetSymbolAddress(&p_Beh, g_Bemb_h); cudaGetSymbolAddress(&p_Bel, g_Bemb_l);
    cudaGetSymbolAddress(&p_Bgh, g_Bg_h);   cudaGetSymbolAddress(&p_Bgl, g_Bg_l);

    float* hbuf[2]  = { (float*)p_h0, (float*)p_h1 };
    __nv_bfloat16* hhbuf[2] = { (__nv_bfloat16*)p_hh0, (__nv_bfloat16*)p_hh1 };
    __nv_bfloat16* hlbuf[2] = { (__nv_bfloat16*)p_hl0, (__nv_bfloat16*)p_hl1 };
    __nv_bfloat16 *ah = (__nv_bfloat16*)p_ah, *al = (__nv_bfloat16*)p_al;
    __nv_bfloat16 *xh = (__nv_bfloat16*)p_xh, *xl = (__nv_bfloat16*)p_xl;
    __nv_bfloat16 *Beh = (__nv_bfloat16*)p_Beh, *Bel = (__nv_bfloat16*)p_Bel;

    cudaFuncSetAttribute(tc_gemm_embed, cudaFuncAttributeMaxDynamicSharedMemorySize, GEMM_SMEM);
    cudaFuncSetAttribute(tc_gemm_gru,   cudaFuncAttributeMaxDynamicSharedMemorySize, GEMM_SMEM);

    const int NB = (NN + 1023) / 1024;

    // CSR build
    detect_k<<<1, 32>>>(edges);
    zero_deg_k<<<128, 256>>>();
    hist_k<<<512, 256>>>(edges);
    scan1_k<<<NB, 1024>>>();
    scan2_k<<<1, 32>>>(NB);
    scan3_k<<<NB, 1024>>>();
    scatter_k<<<512, 256>>>(edges);

    // operand prep (all weights for all steps, up-front)
    convert_x_k<<<(NN * FIN + 255) / 256, 256>>>(x);
    pack_emb_k<<<(CC * FIN + 255) / 256, 256>>>(W_in);
    for (int s = 0; s < NSTEP; ++s) {
        w1_k<<<(384 * 128 + 255) / 256, 256>>>(W_mpnn + (size_t)s * CC * CC, W_ih, s);
        pack_gru_k<<<(512 * 256 + 255) / 256, 256>>>(W_hh, s);
    }

    dim3 grid1((NN + 127) / 128, 1);
    dim3 grid4((NN + 127) / 128, 4);

    // h(buf0) = x @ W_in^T
    tc_gemm_embed<<<grid1, 256, GEMM_SMEM>>>(xh, xl, Beh, Bel,
                                             hbuf[0], hhbuf[0], hlbuf[0], NN);

    void *p_Bgh_s, *p_Bgl_s;
    int cur = 0;
    for (int step = 0; step < NSTEP; ++step) {
        // agg = segment_sum(h[src]) (reassociated past W_mpnn)
        aggregate_k<<<NN / 8, 256>>>(hbuf[cur]);

        __nv_bfloat16* Bgh = (__nv_bfloat16*)p_Bgh + (size_t)step * 512 * 256;
        __nv_bfloat16* Bgl = (__nv_bfloat16*)p_Bgl + (size_t)step * 512 * 256;
        tc_gemm_gru<<<grid4, 256, GEMM_SMEM>>>(ah, al, hhbuf[cur], hlbuf[cur],
                                               Bgh, Bgl,
                                               hbuf[cur], hbuf[1 - cur],
                                               hhbuf[1 - cur], hlbuf[1 - cur],
                                               b_ih, b_hh, NN);
        cur = 1 - cur;
    }

    zero_colsum_k<<<1, 128>>>();
    reduce_cols_k<<<2048, 128>>>(hbuf[cur]);
    finalize_k<<<1, 32>>>(W_pred, b_pred, out);
    (void)p_Bgh_s; (void)p_Bgl_s;
}

// round 6
// speedup vs baseline: 1.0897x; 1.0409x over previous
#include <cuda_runtime.h>
#include <cuda_bf16.h>
#include <math.h>
#include <stdint.h>

#define NN    100000
#define EE    1600000
#define CC    128
#define FIN   64
#define NSTEP 4
#define NEG_SLOPE 0.01f

// ---------------- scratch (static device globals) ----------------
__device__ __align__(256) float g_h0[(size_t)NN * CC], g_h1[(size_t)NN * CC];
__device__ __align__(256) __nv_bfloat16 g_hh0[(size_t)NN * CC], g_hl0[(size_t)NN * CC];
__device__ __align__(256) __nv_bfloat16 g_hh1[(size_t)NN * CC], g_hl1[(size_t)NN * CC];
__device__ __align__(256) __nv_bfloat16 g_ah[(size_t)NN * CC], g_al[(size_t)NN * CC];
__device__ __align__(256) __nv_bfloat16 g_xh[(size_t)NN * FIN], g_xl[(size_t)NN * FIN];
__device__ __align__(256) __nv_bfloat16 g_Bemb_h[CC * FIN], g_Bemb_l[CC * FIN];
__device__ __align__(256) float g_W1[NSTEP][384 * 128];
__device__ __align__(256) __nv_bfloat16 g_Bg_h[NSTEP][512 * 256];
__device__ __align__(256) __nv_bfloat16 g_Bg_l[NSTEP][512 * 256];
__device__ int   g_deg[NN];
__device__ int   g_rowstart[NN + 1];
__device__ int   g_cursor[NN];
__device__ int   g_csrsrc[EE];
__device__ int   g_blocksum[128];
__device__ int   g_blockoff[128];
__device__ int   g_is64;
__device__ float g_colsum[CC];

// ---------------- helpers ----------------
__device__ __forceinline__ uint32_t smem_u32(const void* p) {
    uint32_t a;
    asm("{ .reg .u64 t; cvta.to.shared.u64 t, %1; cvt.u32.u64 %0, t; }" : "=r"(a) : "l"(p));
    return a;
}
__device__ __forceinline__ void cp16(uint32_t dst, const void* src, int sz) {
    asm volatile("cp.async.cg.shared.global [%0], [%1], 16, %2;"
                 :: "r"(dst), "l"(src), "r"(sz));
}
#define CP_COMMIT() asm volatile("cp.async.commit_group;" ::: "memory")
#define CP_WAIT0()  asm volatile("cp.async.wait_group 0;" ::: "memory")

#define LDSM_X4(r0, r1, r2, r3, addr)                                        \
    asm volatile("ldmatrix.sync.aligned.m8n8.x4.shared.b16 {%0,%1,%2,%3}, [%4];" \
                 : "=r"(r0), "=r"(r1), "=r"(r2), "=r"(r3) : "r"(addr))

__device__ __forceinline__ void mma_bf16(float* d, const uint32_t* a, const uint32_t* b) {
    asm volatile(
        "mma.sync.aligned.m16n8k16.row.col.f32.bf16.bf16.f32 "
        "{%0,%1,%2,%3}, {%4,%5,%6,%7}, {%8,%9}, {%0,%1,%2,%3};"
        : "+f"(d[0]), "+f"(d[1]), "+f"(d[2]), "+f"(d[3])
        : "r"(a[0]), "r"(a[1]), "r"(a[2]), "r"(a[3]), "r"(b[0]), "r"(b[1]));
}
__device__ __forceinline__ void split1(float v, __nv_bfloat16& hi, __nv_bfloat16& lo) {
    hi = __float2bfloat16(v);
    lo = __float2bfloat16(v - __bfloat162float(hi));
}

// ---------------- edge dtype detection ----------------
__global__ void detect_k(const void* __restrict__ edges) {
    if (threadIdx.x == 0 && blockIdx.x == 0) {
        const long long* p = (const long long*)edges;
        int is64 = 1;
        for (int i = 0; i < 256; i++) {
            long long v = p[i];
            if (v < 0 || v >= (long long)NN) { is64 = 0; break; }
        }
        g_is64 = is64;
    }
}
__device__ __forceinline__ int edge_at(const void* edges, int which, int e, bool is64) {
    if (is64) return (int)((const long long*)edges)[(size_t)which * EE + e];
    return ((const int*)edges)[(size_t)which * EE + e];
}

// ---------------- CSR build ----------------
__global__ void zero_deg_k() {
    for (int i = blockIdx.x * blockDim.x + threadIdx.x; i < NN; i += gridDim.x * blockDim.x)
        g_deg[i] = 0;
}
__global__ void hist_k(const void* __restrict__ edges) {
    bool is64 = g_is64;
    for (int e = blockIdx.x * blockDim.x + threadIdx.x; e < EE; e += gridDim.x * blockDim.x)
        atomicAdd(&g_deg[edge_at(edges, 1, e, is64)], 1);
}
__global__ void scan1_k() {
    __shared__ int s[1024];
    int tid = threadIdx.x;
    int i = blockIdx.x * 1024 + tid;
    int v = (i < NN) ? g_deg[i] : 0;
    s[tid] = v;
    __syncthreads();
    for (int off = 1; off < 1024; off <<= 1) {
        int t = (tid >= off) ? s[tid - off] : 0;
        __syncthreads();
        s[tid] += t;
        __syncthreads();
    }
    if (i < NN) g_rowstart[i] = s[tid] - v;
    if (tid == 1023) g_blocksum[blockIdx.x] = s[1023];
}
__global__ void scan2_k(int nb) {
    if (threadIdx.x == 0 && blockIdx.x == 0) {
        int acc = 0;
        for (int b = 0; b < nb; b++) { int t = g_blocksum[b]; g_blockoff[b] = acc; acc += t; }
        g_rowstart[NN] = acc;
    }
}
__global__ void scan3_k() {
    int i = blockIdx.x * 1024 + threadIdx.x;
    if (i < NN) {
        int v = g_rowstart[i] + g_blockoff[blockIdx.x];
        g_rowstart[i] = v;
        g_cursor[i] = v;
    }
}
__global__ void scatter_k(const void* __restrict__ edges) {
    bool is64 = g_is64;
    for (int e = blockIdx.x * blockDim.x + threadIdx.x; e < EE; e += gridDim.x * blockDim.x) {
        int src = edge_at(edges, 0, e, is64);
        int dst = edge_at(edges, 1, e, is64);
        g_csrsrc[atomicAdd(&g_cursor[dst], 1)] = src;
    }
}

// ---------------- operand / weight prep ----------------
__global__ void convert_x_k(const float* __restrict__ x) {
    int i = blockIdx.x * blockDim.x + threadIdx.x;
    if (i >= NN * FIN) return;
    split1(x[i], g_xh[i], g_xl[i]);
}
__global__ void pack_emb_k(const float* __restrict__ Win) {
    int i = blockIdx.x * blockDim.x + threadIdx.x;
    if (i >= CC * FIN) return;
    split1(Win[i], g_Bemb_h[i], g_Bemb_l[i]);
}
__global__ void w1_k(const float* __restrict__ Wm, const float* __restrict__ Wih, int step) {
    int i = blockIdx.x * blockDim.x + threadIdx.x;
    if (i >= 384 * 128) return;
    int n = i >> 7, k = i & 127;
    const float* wm = Wm + k * 128;
    const float* wi = Wih + n * 128;
    float s = 0.f;
#pragma unroll 8
    for (int j = 0; j < 128; ++j) s = fmaf(wm[j], wi[j], s);
    g_W1[step][i] = s;
}
__global__ void pack_gru_k(const float* __restrict__ Whh, int step) {
    int i = blockIdx.x * blockDim.x + threadIdx.x;
    if (i >= 512 * 256) return;
    int np = i >> 8, k = i & 255;
    int y = np >> 7, gate = (np >> 5) & 3, cl = np & 31;
    int c = y * 32 + cl;
    float v;
    if (gate < 3) {
        int lr = gate * 128 + c;
        v = (k < 128) ? g_W1[step][lr * 128 + k] : Whh[lr * 128 + (k - 128)];
    } else {
        v = (k < 128) ? 0.f : Whh[(256 + c) * 128 + (k - 128)];
    }
    split1(v, g_Bg_h[step][i], g_Bg_l[step][i]);
}

// ---------------- shared gemm config ----------------
#define ST 20
#define STG_WORDS (4 * 128 * ST)
#define GEMM_SMEM (2 * STG_WORDS * 4)

// fragment compute via ldmatrix: shared by both gemms
// arrays in stage: AH @0, AL @128*ST, BH @2*128*ST, BL @3*128*ST (word offsets)
#define GEMM_MAINLOOP_BODY(sAH_a, sAL_a, sBH_a, sBL_a)                                   \
    _Pragma("unroll")                                                                    \
    for (int kk2 = 0; kk2 < 2; ++kk2) {                                                  \
        const int kw = kk2 * 8;                                                          \
        const int q = lane >> 3, rq = lane & 7;                                          \
        uint32_t bh[4][2], bl[4][2];                                                     \
        {                                                                                \
            int brow = (q >> 1) * 8 + rq;                                                \
            int bword = kw + (q & 1) * 4;                                                \
            _Pragma("unroll")                                                            \
            for (int ntp = 0; ntp < 2; ++ntp) {                                          \
                int n0 = wc * 32 + ntp * 16;                                             \
                uint32_t off = (uint32_t)((n0 + brow) * ST + bword) * 4;                 \
                LDSM_X4(bh[ntp * 2][0], bh[ntp * 2][1],                                  \
                        bh[ntp * 2 + 1][0], bh[ntp * 2 + 1][1], (sBH_a) + off);          \
                LDSM_X4(bl[ntp * 2][0], bl[ntp * 2][1],                                  \
                        bl[ntp * 2 + 1][0], bl[ntp * 2 + 1][1], (sBL_a) + off);          \
            }                                                                            \
        }                                                                                \
        int arow = (q & 1) * 8 + rq;                                                     \
        int aword = kw + (q >> 1) * 4;                                                   \
        _Pragma("unroll")                                                                \
        for (int mt = 0; mt < 4; mt++) {                                                 \
            int m0 = wr * 64 + mt * 16;                                                  \
            uint32_t off = (uint32_t)((m0 + arow) * ST + aword) * 4;                     \
            uint32_t ah[4], al[4];                                                       \
            LDSM_X4(ah[0], ah[1], ah[2], ah[3], (sAH_a) + off);                          \
            LDSM_X4(al[0], al[1], al[2], al[3], (sAL_a) + off);                          \
            _Pragma("unroll")                                                            \
            for (int nt = 0; nt < 4; nt++) {                                             \
                mma_bf16(acc[mt][nt], ah, bh[nt]);                                       \
                mma_bf16(acc[mt][nt], ah, bl[nt]);                                       \
                mma_bf16(acc[mt][nt], al, bh[nt]);                                       \
            }                                                                            \
        }                                                                                \
    }

// ---------------- embed gemm: h0 = x @ Win^T (K=64) ----------------
__global__ void __launch_bounds__(256, 2) tc_gemm_embed(
    const __nv_bfloat16* __restrict__ Ah, const __nv_bfloat16* __restrict__ Al,
    const __nv_bfloat16* __restrict__ Bh, const __nv_bfloat16* __restrict__ Bl,
    float* __restrict__ C, __nv_bfloat16* __restrict__ Oh, __nv_bfloat16* __restrict__ Ol,
    int M)
{
    extern __shared__ uint32_t dsm[];
    const uint32_t sbase = smem_u32(dsm);
    const int tid = threadIdx.x, lane = tid & 31, warp = tid >> 5;
    const int wr = warp & 1, wc = warp >> 1, g = lane >> 2, t = lane & 3;
    const int row0 = blockIdx.x * 128;

    float acc[4][4][4];
#pragma unroll
    for (int i = 0; i < 4; i++)
#pragma unroll
        for (int j = 0; j < 4; j++)
#pragma unroll
            for (int k = 0; k < 4; k++) acc[i][j][k] = 0.f;

    auto load_stage = [&](int buf, int kt) {
        const uint32_t stg = sbase + (uint32_t)buf * STG_WORDS * 4;
#pragma unroll
        for (int it = 0; it < 8; ++it) {
            int idx = tid + it * 256;
            int arr = idx >> 9, rem = idx & 511;
            int r = rem >> 2, c16 = rem & 3;
            int gk = kt + c16 * 8;
            uint32_t dst = stg + (uint32_t)(arr * 128 * ST + r * ST + c16 * 4) * 4;
            const __nv_bfloat16* src;
            int sz = 16;
            if (arr < 2) {
                int grow = row0 + r;
                int srow = (grow < M) ? grow : 0;
                if (grow >= M) sz = 0;
                src = (arr == 0 ? Ah : Al) + (size_t)srow * FIN + gk;
            } else {
                src = (arr == 2 ? Bh : Bl) + (size_t)r * FIN + gk;
            }
            cp16(dst, src, sz);
        }
    };

    load_stage(0, 0);
    CP_COMMIT();
    for (int ch = 0; ch < 2; ++ch) {
        CP_WAIT0();
        __syncthreads();
        if (ch == 0) { load_stage(1, 32); CP_COMMIT(); }
        const uint32_t S = sbase + (uint32_t)(ch & 1) * STG_WORDS * 4;
        const uint32_t sAH = S, sAL = S + 128 * ST * 4;
        const uint32_t sBH = S + 2 * 128 * ST * 4, sBL = S + 3 * 128 * ST * 4;
        GEMM_MAINLOOP_BODY(sAH, sAL, sBH, sBL)
        __syncthreads();
    }

#pragma unroll
    for (int mt = 0; mt < 4; mt++) {
        int rbase = row0 + wr * 64 + mt * 16 + g;
#pragma unroll
        for (int nt = 0; nt < 4; nt++) {
            int col = wc * 32 + nt * 8 + 2 * t;
#pragma unroll
            for (int half = 0; half < 2; ++half) {
                int rr = rbase + half * 8;
                if (rr >= M) continue;
                float v0 = acc[mt][nt][half * 2], v1 = acc[mt][nt][half * 2 + 1];
                *reinterpret_cast<float2*>(C + (size_t)rr * CC + col) = make_float2(v0, v1);
                __nv_bfloat16 h0, l0, h1, l1;
                split1(v0, h0, l0); split1(v1, h1, l1);
                __nv_bfloat162 hp; hp.x = h0; hp.y = h1;
                __nv_bfloat162 lp; lp.x = l0; lp.y = l1;
                *reinterpret_cast<__nv_bfloat162*>(Oh + (size_t)rr * CC + col) = hp;
                *reinterpret_cast<__nv_bfloat162*>(Ol + (size_t)rr * CC + col) = lp;
            }
        }
    }
}

// ---------------- GRU gemm with fused gate epilogue ----------------
__global__ void __launch_bounds__(256, 2) tc_gemm_gru(
    const __nv_bfloat16* __restrict__ Aah, const __nv_bfloat16* __restrict__ Aal,
    const __nv_bfloat16* __restrict__ Ahh, const __nv_bfloat16* __restrict__ Ahl,
    const __nv_bfloat16* __restrict__ Bh,  const __nv_bfloat16* __restrict__ Bl,
    const float* __restrict__ h_in, float* __restrict__ h_out,
    __nv_bfloat16* __restrict__ hh_out, __nv_bfloat16* __restrict__ hl_out,
    const float* __restrict__ bih, const float* __restrict__ bhh,
    int M)
{
    extern __shared__ uint32_t dsm[];
    const uint32_t sbase = smem_u32(dsm);
    const int tid = threadIdx.x, lane = tid & 31, warp = tid >> 5;
    const int wr = warp & 1, wc = warp >> 1, g = lane >> 2, t = lane & 3;
    const int row0 = blockIdx.x * 128;
    const int col0 = blockIdx.y * 128;

    float acc[4][4][4];
#pragma unroll
    for (int i = 0; i < 4; i++)
#pragma unroll
        for (int j = 0; j < 4; j++)
#pragma unroll
            for (int k = 0; k < 4; k++) acc[i][j][k] = 0.f;

    auto load_stage = [&](int buf, int kt) {
        const uint32_t stg = sbase + (uint32_t)buf * STG_WORDS * 4;
#pragma unroll
        for (int it = 0; it < 8; ++it) {
            int idx = tid + it * 256;
            int arr = idx >> 9, rem = idx & 511;
            int r = rem >> 2, c16 = rem & 3;
            int gk = kt + c16 * 8;
            uint32_t dst = stg + (uint32_t)(arr * 128 * ST + r * ST + c16 * 4) * 4;
            const __nv_bfloat16* src;
            int sz = 16;
            if (arr < 2) {
                int grow = row0 + r;
                int srow = (grow < M) ? grow : 0;
                if (grow >= M) sz = 0;
                if (gk < 128) src = (arr == 0 ? Aah : Aal) + (size_t)srow * CC + gk;
                else          src = (arr == 0 ? Ahh : Ahl) + (size_t)srow * CC + (gk - 128);
            } else {
                src = (arr == 2 ? Bh : Bl) + (size_t)(col0 + r) * 256 + gk;
            }
            cp16(dst, src, sz);
        }
    };

    load_stage(0, 0);
    CP_COMMIT();
    for (int ch = 0; ch < 8; ++ch) {
        CP_WAIT0();
        __syncthreads();
        if (ch + 1 < 8) { load_stage((ch + 1) & 1, (ch + 1) * 32); CP_COMMIT(); }
        const uint32_t S = sbase + (uint32_t)(ch & 1) * STG_WORDS * 4;
        const uint32_t sAH = S, sAL = S + 128 * ST * 4;
        const uint32_t sBH = S + 2 * 128 * ST * 4, sBL = S + 3 * 128 * ST * 4;
        GEMM_MAINLOOP_BODY(sAH, sAL, sBH, sBL)
        __syncthreads();
    }

    // ---- stage C tile into smem ----
    float* stage = reinterpret_cast<float*>(dsm);
#pragma unroll
    for (int mt = 0; mt < 4; mt++) {
        int r0 = wr * 64 + mt * 16 + g;
#pragma unroll
        for (int nt = 0; nt < 4; nt++) {
            int col = wc * 32 + nt * 8 + 2 * t;
            *reinterpret_cast<float2*>(&stage[r0 * 132 + col]) =
                make_float2(acc[mt][nt][0], acc[mt][nt][1]);
            *reinterpret_cast<float2*>(&stage[(r0 + 8) * 132 + col]) =
                make_float2(acc[mt][nt][2], acc[mt][nt][3]);
        }
    }
    __syncthreads();

    // ---- fused GRU gates: cols {0..31}=r, {32..63}=z, {64..95}=n, {96..127}=Hn ----
    const int y = blockIdx.y;
#pragma unroll
    for (int it = 0; it < 16; ++it) {
        int idx = tid + it * 256;
        int row = idx >> 5, cl = idx & 31;
        int grow = row0 + row;
        if (grow >= M) continue;
        int c = y * 32 + cl;
        const float* sr = &stage[row * 132];
        float Gr = sr[cl], Gz = sr[32 + cl], Gn = sr[64 + cl], Hn = sr[96 + cl];
        float ho = h_in[(size_t)grow * CC + c];
        float r = 1.f / (1.f + expf(-(Gr + bih[c] + bhh[c])));
        float z = 1.f / (1.f + expf(-(Gz + bih[CC + c] + bhh[CC + c])));
        float nn = tanhf((Gn - Hn) + bih[2 * CC + c] + r * (Hn + bhh[2 * CC + c]));
        float hnew = (1.f - z) * nn + z * ho;
        h_out[(size_t)grow * CC + c] = hnew;
        __nv_bfloat16 hi, lo;
        split1(hnew, hi, lo);
        hh_out[(size_t)grow * CC + c] = hi;
        hl_out[(size_t)grow * CC + c] = lo;
    }
}

// ---------------- aggregation ----------------
__global__ void aggregate_k(const float* __restrict__ h_in) {
    int warp = (blockIdx.x * blockDim.x + threadIdx.x) >> 5;
    int lane = threadIdx.x & 31;
    if (warp >= NN) return;
    const float4* m4 = reinterpret_cast<const float4*>(h_in);
    int s = g_rowstart[warp], e = g_rowstart[warp + 1];
    float4 acc = make_float4(0.f, 0.f, 0.f, 0.f);
    int i = s;
    for (; i + 4 <= e; i += 4) {
        int s0 = g_csrsrc[i], s1 = g_csrsrc[i + 1], s2 = g_csrsrc[i + 2], s3 = g_csrsrc[i + 3];
        float4 v0 = m4[(size_t)s0 * 32 + lane];
        float4 v1 = m4[(size_t)s1 * 32 + lane];
        float4 v2 = m4[(size_t)s2 * 32 + lane];
        float4 v3 = m4[(size_t)s3 * 32 + lane];
        acc.x += (v0.x + v1.x) + (v2.x + v3.x);
        acc.y += (v0.y + v1.y) + (v2.y + v3.y);
        acc.z += (v0.z + v1.z) + (v2.z + v3.z);
        acc.w += (v0.w + v1.w) + (v2.w + v3.w);
    }
    for (; i < e; ++i) {
        float4 v = m4[(size_t)g_csrsrc[i] * 32 + lane];
        acc.x += v.x; acc.y += v.y; acc.z += v.z; acc.w += v.w;
    }
    __nv_bfloat16 h0, l0, h1, l1, h2, l2, h3, l3;
    split1(acc.x, h0, l0); split1(acc.y, h1, l1);
    split1(acc.z, h2, l2); split1(acc.w, h3, l3);
    size_t off = (size_t)warp * CC + lane * 4;
    __nv_bfloat162 hp0; hp0.x = h0; hp0.y = h1;
    __nv_bfloat162 hp1; hp1.x = h2; hp1.y = h3;
    __nv_bfloat162 lp0; lp0.x = l0; lp0.y = l1;
    __nv_bfloat162 lp1; lp1.x = l2; lp1.y = l3;
    *reinterpret_cast<__nv_bfloat162*>(g_ah + off)     = hp0;
    *reinterpret_cast<__nv_bfloat162*>(g_ah + off + 2) = hp1;
    *reinterpret_cast<__nv_bfloat162*>(g_al + off)     = lp0;
    *reinterpret_cast<__nv_bfloat162*>(g_al + off + 2) = lp1;
}

// ---------------- readout ----------------
__global__ void zero_colsum_k() { if (threadIdx.x < CC) g_colsum[threadIdx.x] = 0.f; }

__global__ void reduce_cols_k(const float* __restrict__ h) {
    int c = threadIdx.x;
    float acc = 0.f;
    for (int n = blockIdx.x; n < NN; n += gridDim.x) {
        float v = h[(size_t)n * CC + c];
        acc += (v >= 0.f) ? v : NEG_SLOPE * v;
    }
    atomicAdd(&g_colsum[c], acc);
}

__global__ void finalize_k(const float* __restrict__ wpred, const float* __restrict__ bpred,
                           float* __restrict__ out) {
    int lane = threadIdx.x;
    float s = 0.f;
    for (int c = lane; c < CC; c += 32) s += g_colsum[c] * wpred[c];
    for (int o = 16; o; o >>= 1) s += __shfl_xor_sync(0xFFFFFFFFu, s, o);
    if (lane == 0) out[0] = s * (1.0f / (float)NN) + bpred[0];
}

// ---------------- launch ----------------
extern "C" void kernel_launch(void* const* d_in, const int* in_sizes, int n_in,
                              void* d_out, int out_size) {
    const float* x      = (const float*)d_in[0];
    const void*  edges  = d_in[1];
    const float* W_in   = (const float*)d_in[2];
    const float* W_mpnn = (const float*)d_in[3];
    const float* W_ih   = (const float*)d_in[4];
    const float* W_hh   = (const float*)d_in[5];
    const float* b_ih   = (const float*)d_in[6];
    const float* b_hh   = (const float*)d_in[7];
    const float* W_pred = (const float*)d_in[8];
    const float* b_pred = (const float*)d_in[9];
    float* out = (float*)d_out;

    void *p_h0, *p_h1, *p_hh0, *p_hl0, *p_hh1, *p_hl1, *p_ah, *p_al;
    void *p_xh, *p_xl, *p_Beh, *p_Bel, *p_Bgh, *p_Bgl;
    cudaGetSymbolAddress(&p_h0, g_h0);   cudaGetSymbolAddress(&p_h1, g_h1);
    cudaGetSymbolAddress(&p_hh0, g_hh0); cudaGetSymbolAddress(&p_hl0, g_hl0);
    cudaGetSymbolAddress(&p_hh1, g_hh1); cudaGetSymbolAddress(&p_hl1, g_hl1);
    cudaGetSymbolAddress(&p_ah, g_ah);   cudaGetSymbolAddress(&p_al, g_al);
    cudaGetSymbolAddress(&p_xh, g_xh);   cudaGetSymbolAddress(&p_xl, g_xl);
    cudaGetSymbolAddress(&p_Beh, g_Bemb_h); cudaGetSymbolAddress(&p_Bel, g_Bemb_l);
    cudaGetSymbolAddress(&p_Bgh, g_Bg_h);   cudaGetSymbolAddress(&p_Bgl, g_Bg_l);

    float* hbuf[2]  = { (float*)p_h0, (float*)p_h1 };
    __nv_bfloat16* hhbuf[2] = { (__nv_bfloat16*)p_hh0, (__nv_bfloat16*)p_hh1 };
    __nv_bfloat16* hlbuf[2] = { (__nv_bfloat16*)p_hl0, (__nv_bfloat16*)p_hl1 };
    __nv_bfloat16 *ah = (__nv_bfloat16*)p_ah, *al = (__nv_bfloat16*)p_al;
    __nv_bfloat16 *xh = (__nv_bfloat16*)p_xh, *xl = (__nv_bfloat16*)p_xl;
    __nv_bfloat16 *Beh = (__nv_bfloat16*)p_Beh, *Bel = (__nv_bfloat16*)p_Bel;

    cudaFuncSetAttribute(tc_gemm_embed, cudaFuncAttributeMaxDynamicSharedMemorySize, GEMM_SMEM);
    cudaFuncSetAttribute(tc_gemm_gru,   cudaFuncAttributeMaxDynamicSharedMemorySize, GEMM_SMEM);

    const int NB = (NN + 1023) / 1024;

    // CSR build
    detect_k<<<1, 32>>>(edges);
    zero_deg_k<<<128, 256>>>();
    hist_k<<<512, 256>>>(edges);
    scan1_k<<<NB, 1024>>>();
    scan2_k<<<1, 32>>>(NB);
    scan3_k<<<NB, 1024>>>();
    scatter_k<<<512, 256>>>(edges);

    // operand prep
    convert_x_k<<<(NN * FIN + 255) / 256, 256>>>(x);
    pack_emb_k<<<(CC * FIN + 255) / 256, 256>>>(W_in);
    for (int s = 0; s < NSTEP; ++s) {
        w1_k<<<(384 * 128 + 255) / 256, 256>>>(W_mpnn + (size_t)s * CC * CC, W_ih, s);
        pack_gru_k<<<(512 * 256 + 255) / 256, 256>>>(W_hh, s);
    }

    dim3 grid1((NN + 127) / 128, 1);
    dim3 grid4((NN + 127) / 128, 4);

    tc_gemm_embed<<<grid1, 256, GEMM_SMEM>>>(xh, xl, Beh, Bel,
                                             hbuf[0], hhbuf[0], hlbuf[0], NN);

    int cur = 0;
    for (int step = 0; step < NSTEP; ++step) {
        aggregate_k<<<NN / 8, 256>>>(hbuf[cur]);

        __nv_bfloat16* Bgh = (__nv_bfloat16*)p_Bgh + (size_t)step * 512 * 256;
        __nv_bfloat16* Bgl = (__nv_bfloat16*)p_Bgl + (size_t)step * 512 * 256;
        tc_gemm_gru<<<grid4, 256, GEMM_SMEM>>>(ah, al, hhbuf[cur], hlbuf[cur],
                                               Bgh, Bgl,
                                               hbuf[cur], hbuf[1 - cur],
                                               hhbuf[1 - cur], hlbuf[1 - cur],
                                               b_ih, b_hh, NN);
        cur = 1 - cur;
    }

    zero_colsum_k<<<1, 128>>>();
    reduce_cols_k<<<2048, 128>>>(hbuf[cur]);
    finalize_k<<<1, 32>>>(W_pred, b_pred, out);
}

// round 7
// speedup vs baseline: 1.0993x; 1.0088x over previous
#include <cuda_runtime.h>
#include <cuda_bf16.h>
#include <math.h>
#include <stdint.h>

#define NN    100000
#define EE    1600000
#define CC    128
#define FIN   64
#define NSTEP 4
#define NEG_SLOPE 0.01f

// ---------------- scratch (static device globals) ----------------
__device__ __align__(256) __nv_bfloat16 g_hh0[(size_t)NN * CC], g_hl0[(size_t)NN * CC];
__device__ __align__(256) __nv_bfloat16 g_hh1[(size_t)NN * CC], g_hl1[(size_t)NN * CC];
__device__ __align__(256) __nv_bfloat16 g_ah[(size_t)NN * CC], g_al[(size_t)NN * CC];
__device__ __align__(256) __nv_bfloat16 g_xh[(size_t)NN * FIN], g_xl[(size_t)NN * FIN];
__device__ __align__(256) __nv_bfloat16 g_Bemb_h[CC * FIN], g_Bemb_l[CC * FIN];
__device__ __align__(256) float g_W1[NSTEP][384 * 128];
__device__ __align__(256) __nv_bfloat16 g_Bg_h[NSTEP][512 * 256];
__device__ __align__(256) __nv_bfloat16 g_Bg_l[NSTEP][512 * 256];
__device__ int   g_deg[NN];
__device__ int   g_rowstart[NN + 1];
__device__ int   g_cursor[NN];
__device__ int   g_csrsrc[EE];
__device__ int   g_blocksum[128];
__device__ int   g_blockoff[128];
__device__ int   g_is64;
__device__ float g_colsum[CC];

// ---------------- helpers ----------------
__device__ __forceinline__ uint32_t smem_u32(const void* p) {
    uint32_t a;
    asm("{ .reg .u64 t; cvta.to.shared.u64 t, %1; cvt.u32.u64 %0, t; }" : "=r"(a) : "l"(p));
    return a;
}
__device__ __forceinline__ void cp16(uint32_t dst, const void* src, int sz) {
    asm volatile("cp.async.cg.shared.global [%0], [%1], 16, %2;"
                 :: "r"(dst), "l"(src), "r"(sz));
}
#define CP_COMMIT() asm volatile("cp.async.commit_group;" ::: "memory")
#define CP_WAIT0()  asm volatile("cp.async.wait_group 0;" ::: "memory")

#define LDSM_X4(r0, r1, r2, r3, addr)                                        \
    asm volatile("ldmatrix.sync.aligned.m8n8.x4.shared.b16 {%0,%1,%2,%3}, [%4];" \
                 : "=r"(r0), "=r"(r1), "=r"(r2), "=r"(r3) : "r"(addr))

__device__ __forceinline__ void mma_bf16(float* d, const uint32_t* a, const uint32_t* b) {
    asm volatile(
        "mma.sync.aligned.m16n8k16.row.col.f32.bf16.bf16.f32 "
        "{%0,%1,%2,%3}, {%4,%5,%6,%7}, {%8,%9}, {%0,%1,%2,%3};"
        : "+f"(d[0]), "+f"(d[1]), "+f"(d[2]), "+f"(d[3])
        : "r"(a[0]), "r"(a[1]), "r"(a[2]), "r"(a[3]), "r"(b[0]), "r"(b[1]));
}
__device__ __forceinline__ void split1(float v, __nv_bfloat16& hi, __nv_bfloat16& lo) {
    hi = __float2bfloat16(v);
    lo = __float2bfloat16(v - __bfloat162float(hi));
}
__device__ __forceinline__ float2 bf2_to_f2(uint32_t u) {
    __nv_bfloat162 t = *reinterpret_cast<__nv_bfloat162*>(&u);
    return make_float2(__bfloat162float(t.x), __bfloat162float(t.y));
}

// ---------------- edge dtype detection ----------------
__global__ void detect_k(const void* __restrict__ edges) {
    if (threadIdx.x == 0 && blockIdx.x == 0) {
        const long long* p = (const long long*)edges;
        int is64 = 1;
        for (int i = 0; i < 256; i++) {
            long long v = p[i];
            if (v < 0 || v >= (long long)NN) { is64 = 0; break; }
        }
        g_is64 = is64;
    }
}
__device__ __forceinline__ int edge_at(const void* edges, int which, int e, bool is64) {
    if (is64) return (int)((const long long*)edges)[(size_t)which * EE + e];
    return ((const int*)edges)[(size_t)which * EE + e];
}

// ---------------- CSR build ----------------
__global__ void zero_deg_k() {
    for (int i = blockIdx.x * blockDim.x + threadIdx.x; i < NN; i += gridDim.x * blockDim.x)
        g_deg[i] = 0;
}
__global__ void hist_k(const void* __restrict__ edges) {
    bool is64 = g_is64;
    for (int e = blockIdx.x * blockDim.x + threadIdx.x; e < EE; e += gridDim.x * blockDim.x)
        atomicAdd(&g_deg[edge_at(edges, 1, e, is64)], 1);
}
__global__ void scan1_k() {
    __shared__ int s[1024];
    int tid = threadIdx.x;
    int i = blockIdx.x * 1024 + tid;
    int v = (i < NN) ? g_deg[i] : 0;
    s[tid] = v;
    __syncthreads();
    for (int off = 1; off < 1024; off <<= 1) {
        int t = (tid >= off) ? s[tid - off] : 0;
        __syncthreads();
        s[tid] += t;
        __syncthreads();
    }
    if (i < NN) g_rowstart[i] = s[tid] - v;
    if (tid == 1023) g_blocksum[blockIdx.x] = s[1023];
}
__global__ void scan2_k(int nb) {
    if (threadIdx.x == 0 && blockIdx.x == 0) {
        int acc = 0;
        for (int b = 0; b < nb; b++) { int t = g_blocksum[b]; g_blockoff[b] = acc; acc += t; }
        g_rowstart[NN] = acc;
    }
}
__global__ void scan3_k() {
    int i = blockIdx.x * 1024 + threadIdx.x;
    if (i < NN) {
        int v = g_rowstart[i] + g_blockoff[blockIdx.x];
        g_rowstart[i] = v;
        g_cursor[i] = v;
    }
}
__global__ void scatter_k(const void* __restrict__ edges) {
    bool is64 = g_is64;
    for (int e = blockIdx.x * blockDim.x + threadIdx.x; e < EE; e += gridDim.x * blockDim.x) {
        int src = edge_at(edges, 0, e, is64);
        int dst = edge_at(edges, 1, e, is64);
        g_csrsrc[atomicAdd(&g_cursor[dst], 1)] = src;
    }
}

// ---------------- operand / weight prep ----------------
__global__ void convert_x_k(const float* __restrict__ x) {
    int i = blockIdx.x * blockDim.x + threadIdx.x;
    if (i >= NN * FIN) return;
    split1(x[i], g_xh[i], g_xl[i]);
}
__global__ void pack_emb_k(const float* __restrict__ Win) {
    int i = blockIdx.x * blockDim.x + threadIdx.x;
    if (i >= CC * FIN) return;
    split1(Win[i], g_Bemb_h[i], g_Bemb_l[i]);
}
__global__ void w1_k(const float* __restrict__ Wm, const float* __restrict__ Wih, int step) {
    int i = blockIdx.x * blockDim.x + threadIdx.x;
    if (i >= 384 * 128) return;
    int n = i >> 7, k = i & 127;
    const float* wm = Wm + k * 128;
    const float* wi = Wih + n * 128;
    float s = 0.f;
#pragma unroll 8
    for (int j = 0; j < 128; ++j) s = fmaf(wm[j], wi[j], s);
    g_W1[step][i] = s;
}
// row n' -> (y=n'>>7, gate=(n'>>5)&3, cl=n'&31, channel c=y*32+cl)
__global__ void pack_gru_k(const float* __restrict__ Whh, int step) {
    int i = blockIdx.x * blockDim.x + threadIdx.x;
    if (i >= 512 * 256) return;
    int np = i >> 8, k = i & 255;
    int y = np >> 7, gate = (np >> 5) & 3, cl = np & 31;
    int c = y * 32 + cl;
    float v;
    if (gate < 3) {
        int lr = gate * 128 + c;
        v = (k < 128) ? g_W1[step][lr * 128 + k] : Whh[lr * 128 + (k - 128)];
    } else {
        v = (k < 128) ? 0.f : Whh[(256 + c) * 128 + (k - 128)];
    }
    split1(v, g_Bg_h[step][i], g_Bg_l[step][i]);
}

// ================= embed gemm (round-6 layout, BM=128) =================
#define ST 20
#define STG_WORDS (4 * 128 * ST)
#define EMB_SMEM (2 * STG_WORDS * 4)

__global__ void __launch_bounds__(256, 2) tc_gemm_embed(
    const __nv_bfloat16* __restrict__ Ah, const __nv_bfloat16* __restrict__ Al,
    const __nv_bfloat16* __restrict__ Bh, const __nv_bfloat16* __restrict__ Bl,
    __nv_bfloat16* __restrict__ Oh, __nv_bfloat16* __restrict__ Ol,
    int M)
{
    extern __shared__ uint32_t dsm[];
    const uint32_t sbase = smem_u32(dsm);
    const int tid = threadIdx.x, lane = tid & 31, warp = tid >> 5;
    const int wr = warp & 1, wc = warp >> 1, g = lane >> 2, t = lane & 3;
    const int q = lane >> 3, rq = lane & 7;
    const int row0 = blockIdx.x * 128;

    float acc[4][4][4];
#pragma unroll
    for (int i = 0; i < 4; i++)
#pragma unroll
        for (int j = 0; j < 4; j++)
#pragma unroll
            for (int k = 0; k < 4; k++) acc[i][j][k] = 0.f;

    auto load_stage = [&](int buf, int kt) {
        const uint32_t stg = sbase + (uint32_t)buf * STG_WORDS * 4;
#pragma unroll
        for (int it = 0; it < 8; ++it) {
            int idx = tid + it * 256;
            int arr = idx >> 9, rem = idx & 511;
            int r = rem >> 2, c16 = rem & 3;
            int gk = kt + c16 * 8;
            uint32_t dst = stg + (uint32_t)(arr * 128 * ST + r * ST + c16 * 4) * 4;
            const __nv_bfloat16* src;
            int sz = 16;
            if (arr < 2) {
                int grow = row0 + r;
                int srow = (grow < M) ? grow : 0;
                if (grow >= M) sz = 0;
                src = (arr == 0 ? Ah : Al) + (size_t)srow * FIN + gk;
            } else {
                src = (arr == 2 ? Bh : Bl) + (size_t)r * FIN + gk;
            }
            cp16(dst, src, sz);
        }
    };

    load_stage(0, 0);
    CP_COMMIT();
    for (int ch = 0; ch < 2; ++ch) {
        CP_WAIT0();
        __syncthreads();
        if (ch == 0) { load_stage(1, 32); CP_COMMIT(); }
        const uint32_t S = sbase + (uint32_t)(ch & 1) * STG_WORDS * 4;
        const uint32_t sAH = S, sAL = S + 128 * ST * 4;
        const uint32_t sBH = S + 2 * 128 * ST * 4, sBL = S + 3 * 128 * ST * 4;
#pragma unroll
        for (int kk2 = 0; kk2 < 2; ++kk2) {
            const int kw = kk2 * 8;
            uint32_t bh[4][2], bl[4][2];
            int brow = (q >> 1) * 8 + rq;
            int bword = kw + (q & 1) * 4;
#pragma unroll
            for (int ntp = 0; ntp < 2; ++ntp) {
                int n0 = wc * 32 + ntp * 16;
                uint32_t off = (uint32_t)((n0 + brow) * ST + bword) * 4;
                LDSM_X4(bh[ntp * 2][0], bh[ntp * 2][1],
                        bh[ntp * 2 + 1][0], bh[ntp * 2 + 1][1], sBH + off);
                LDSM_X4(bl[ntp * 2][0], bl[ntp * 2][1],
                        bl[ntp * 2 + 1][0], bl[ntp * 2 + 1][1], sBL + off);
            }
            int arow = (q & 1) * 8 + rq;
            int aword = kw + (q >> 1) * 4;
#pragma unroll
            for (int mt = 0; mt < 4; mt++) {
                int m0 = wr * 64 + mt * 16;
                uint32_t off = (uint32_t)((m0 + arow) * ST + aword) * 4;
                uint32_t ah[4], al[4];
                LDSM_X4(ah[0], ah[1], ah[2], ah[3], sAH + off);
                LDSM_X4(al[0], al[1], al[2], al[3], sAL + off);
#pragma unroll
                for (int nt = 0; nt < 4; nt++) {
                    mma_bf16(acc[mt][nt], ah, bh[nt]);
                    mma_bf16(acc[mt][nt], ah, bl[nt]);
                    mma_bf16(acc[mt][nt], al, bh[nt]);
                }
            }
        }
        __syncthreads();
    }

#pragma unroll
    for (int mt = 0; mt < 4; mt++) {
        int rbase = row0 + wr * 64 + mt * 16 + g;
#pragma unroll
        for (int nt = 0; nt < 4; nt++) {
            int col = wc * 32 + nt * 8 + 2 * t;
#pragma unroll
            for (int half = 0; half < 2; ++half) {
                int rr = rbase + half * 8;
                if (rr >= M) continue;
                float v0 = acc[mt][nt][half * 2], v1 = acc[mt][nt][half * 2 + 1];
                __nv_bfloat16 h0, l0, h1, l1;
                split1(v0, h0, l0); split1(v1, h1, l1);
                __nv_bfloat162 hp; hp.x = h0; hp.y = h1;
                __nv_bfloat162 lp; lp.x = l0; lp.y = l1;
                *reinterpret_cast<__nv_bfloat162*>(Oh + (size_t)rr * CC + col) = hp;
                *reinterpret_cast<__nv_bfloat162*>(Ol + (size_t)rr * CC + col) = lp;
            }
        }
    }
}

// ================= A-resident GRU gemm, BM=64, all 4 y-blocks per CTA =================
// smem words: A_hi [0, 8448), A_lo [8448, 16896), B region [16896, 27136)
//   B stage s: BH at 16896 + s*5120, BL at +2560   (128 rows x 20 words)
//   epilogue stage: 64 x 132 fp32 at word 16896 (reuses B region between y's)
#define A_ST   132
#define AOFF_LO 8448
#define WB     16896
#define BSTG   5120
#define GRU_SMEM (27136 * 4)

__global__ void __launch_bounds__(256, 2) tc_gemm_gru(
    const __nv_bfloat16* __restrict__ Aah, const __nv_bfloat16* __restrict__ Aal,
    const __nv_bfloat16* __restrict__ Ahh, const __nv_bfloat16* __restrict__ Ahl,
    const __nv_bfloat16* __restrict__ Bh,  const __nv_bfloat16* __restrict__ Bl,
    __nv_bfloat16* __restrict__ hh_out, __nv_bfloat16* __restrict__ hl_out,
    const float* __restrict__ bih, const float* __restrict__ bhh,
    int M)
{
    extern __shared__ uint32_t dsm[];
    const uint32_t sbase = smem_u32(dsm);
    const int tid = threadIdx.x, lane = tid & 31, warp = tid >> 5;
    const int wr = warp & 1, wc = warp >> 1, g = lane >> 2, t = lane & 3;
    const int q = lane >> 3, rq = lane & 7;
    const int row0 = blockIdx.x * 64;

    // ---- load A tile once: 64 rows x 256 k, hi+lo ----
#pragma unroll
    for (int it = 0; it < 16; ++it) {
        int idx = tid + it * 256;            // 0..4095
        int arr = idx >> 11;                 // 0=hi 1=lo
        int rem = idx & 2047;
        int r = rem >> 5, c16 = rem & 31;
        int gk = c16 * 8;
        uint32_t dst = sbase + (uint32_t)((arr ? AOFF_LO : 0) + r * A_ST + c16 * 4) * 4;
        int grow = row0 + r;
        int srow = (grow < M) ? grow : 0;
        int sz = (grow < M) ? 16 : 0;
        const __nv_bfloat16* src;
        if (gk < 128) src = (arr ? Aal : Aah) + (size_t)srow * CC + gk;
        else          src = (arr ? Ahl : Ahh) + (size_t)srow * CC + (gk - 128);
        cp16(dst, src, sz);
    }
    CP_COMMIT();

    auto load_B = [&](int s, int y, int ch) {
        const uint32_t stg = sbase + (uint32_t)(WB + s * BSTG) * 4;
#pragma unroll
        for (int it = 0; it < 4; ++it) {
            int idx = tid + it * 256;        // 0..1023
            int arr = idx >> 9;              // 0=BH 1=BL
            int rem = idx & 511;
            int r = rem >> 2, c16 = rem & 3;
            uint32_t dst = stg + (uint32_t)(arr * 2560 + r * ST + c16 * 4) * 4;
            const __nv_bfloat16* src =
                (arr ? Bl : Bh) + (size_t)(y * 128 + r) * 256 + ch * 32 + c16 * 8;
            cp16(dst, src, 16);
        }
    };

    // per-thread constants for the gate epilogue (cl constant per thread)
    const int cl = tid & 31;

    const uint32_t sAH = sbase, sAL = sbase + AOFF_LO * 4;
    float* stageF = reinterpret_cast<float*>(dsm + WB);

    for (int y = 0; y < 4; ++y) {
        float acc[2][4][4];
#pragma unroll
        for (int i = 0; i < 2; i++)
#pragma unroll
            for (int j = 0; j < 4; j++)
#pragma unroll
                for (int k = 0; k < 4; k++) acc[i][j][k] = 0.f;

        load_B(0, y, 0);
        CP_COMMIT();

        for (int ch = 0; ch < 8; ++ch) {
            CP_WAIT0();
            __syncthreads();
            if (ch + 1 < 8) { load_B((ch + 1) & 1, y, ch + 1); CP_COMMIT(); }

            const uint32_t sB = sbase + (uint32_t)(WB + (ch & 1) * BSTG) * 4;
            const uint32_t sBH = sB, sBL = sB + 2560 * 4;
#pragma unroll
            for (int kk2 = 0; kk2 < 2; ++kk2) {
                const int kw = kk2 * 8;
                uint32_t bh[4][2], bl[4][2];
                int brow = (q >> 1) * 8 + rq;
                int bword = kw + (q & 1) * 4;
#pragma unroll
                for (int ntp = 0; ntp < 2; ++ntp) {
                    int n0 = wc * 32 + ntp * 16;
                    uint32_t off = (uint32_t)((n0 + brow) * ST + bword) * 4;
                    LDSM_X4(bh[ntp * 2][0], bh[ntp * 2][1],
                            bh[ntp * 2 + 1][0], bh[ntp * 2 + 1][1], sBH + off);
                    LDSM_X4(bl[ntp * 2][0], bl[ntp * 2][1],
                            bl[ntp * 2 + 1][0], bl[ntp * 2 + 1][1], sBL + off);
                }
                int arow = (q & 1) * 8 + rq;
                int aword = ch * 16 + kw + (q >> 1) * 4;
#pragma unroll
                for (int mt = 0; mt < 2; mt++) {
                    int m0 = wr * 32 + mt * 16;
                    uint32_t off = (uint32_t)((m0 + arow) * A_ST + aword) * 4;
                    uint32_t ah[4], al[4];
                    LDSM_X4(ah[0], ah[1], ah[2], ah[3], sAH + off);
                    LDSM_X4(al[0], al[1], al[2], al[3], sAL + off);
#pragma unroll
                    for (int nt = 0; nt < 4; nt++) {
                        mma_bf16(acc[mt][nt], ah, bh[nt]);
                        mma_bf16(acc[mt][nt], ah, bl[nt]);
                        mma_bf16(acc[mt][nt], al, bh[nt]);
                    }
                }
            }
            __syncthreads();
        }

        // ---- epilogue: acc -> stage (reuses B smem; all B reads for this y are done) ----
#pragma unroll
        for (int mt = 0; mt < 2; mt++) {
            int r0 = wr * 32 + mt * 16 + g;
#pragma unroll
            for (int nt = 0; nt < 4; nt++) {
                int col = wc * 32 + nt * 8 + 2 * t;
                *reinterpret_cast<float2*>(&stageF[r0 * A_ST + col]) =
                    make_float2(acc[mt][nt][0], acc[mt][nt][1]);
                *reinterpret_cast<float2*>(&stageF[(r0 + 8) * A_ST + col]) =
                    make_float2(acc[mt][nt][2], acc[mt][nt][3]);
            }
        }
        __syncthreads();

        // ---- fused gates: tile cols {0..31}=r, {32..63}=z, {64..95}=n, {96..127}=Hn ----
        {
            int c = y * 32 + cl;
            float b1r = bih[c] + bhh[c];
            float b1z = bih[CC + c] + bhh[CC + c];
            float bin = bih[2 * CC + c];
            float bhn = bhh[2 * CC + c];
#pragma unroll
            for (int it = 0; it < 8; ++it) {
                int idx = tid + it * 256;   // 0..2047
                int row = idx >> 5;
                int grow = row0 + row;
                if (grow >= M) continue;
                const float* sr = &stageF[row * A_ST];
                float Gr = sr[cl], Gz = sr[32 + cl], Gn = sr[64 + cl], Hn = sr[96 + cl];
                size_t o = (size_t)grow * CC + c;
                float ho = __bfloat162float(Ahh[o]) + __bfloat162float(Ahl[o]);
                float r = 1.f / (1.f + expf(-(Gr + b1r)));
                float z = 1.f / (1.f + expf(-(Gz + b1z)));
                float nn = tanhf((Gn - Hn) + bin + r * (Hn + bhn));
                float hnew = (1.f - z) * nn + z * ho;
                __nv_bfloat16 hi, lo;
                split1(hnew, hi, lo);
                hh_out[o] = hi;
                hl_out[o] = lo;
            }
        }
        __syncthreads();   // before next y's B loads overwrite the stage
    }
}

// ---------------- aggregation: agg = CSR-gather-sum of (hh+hl), emit bf16 hi/lo ----------------
__global__ void aggregate_k(const __nv_bfloat16* __restrict__ hh_in,
                            const __nv_bfloat16* __restrict__ hl_in) {
    int warp = (blockIdx.x * blockDim.x + threadIdx.x) >> 5;
    int lane = threadIdx.x & 31;
    if (warp >= NN) return;
    int s = g_rowstart[warp], e = g_rowstart[warp + 1];
    float4 acc = make_float4(0.f, 0.f, 0.f, 0.f);
    const int lo4 = lane * 4;
    for (int i = s; i < e; ++i) {
        size_t off = (size_t)g_csrsrc[i] * CC + lo4;
        uint2 uh = *reinterpret_cast<const uint2*>(hh_in + off);
        uint2 ul = *reinterpret_cast<const uint2*>(hl_in + off);
        float2 h0 = bf2_to_f2(uh.x), h1 = bf2_to_f2(uh.y);
        float2 l0 = bf2_to_f2(ul.x), l1 = bf2_to_f2(ul.y);
        acc.x += h0.x + l0.x;
        acc.y += h0.y + l0.y;
        acc.z += h1.x + l1.x;
        acc.w += h1.y + l1.y;
    }
    __nv_bfloat16 h0, l0, h1, l1, h2, l2, h3, l3;
    split1(acc.x, h0, l0); split1(acc.y, h1, l1);
    split1(acc.z, h2, l2); split1(acc.w, h3, l3);
    size_t off = (size_t)warp * CC + lo4;
    __nv_bfloat162 hp0; hp0.x = h0; hp0.y = h1;
    __nv_bfloat162 hp1; hp1.x = h2; hp1.y = h3;
    __nv_bfloat162 lp0; lp0.x = l0; lp0.y = l1;
    __nv_bfloat162 lp1; lp1.x = l2; lp1.y = l3;
    *reinterpret_cast<__nv_bfloat162*>(g_ah + off)     = hp0;
    *reinterpret_cast<__nv_bfloat162*>(g_ah + off + 2) = hp1;
    *reinterpret_cast<__nv_bfloat162*>(g_al + off)     = lp0;
    *reinterpret_cast<__nv_bfloat162*>(g_al + off + 2) = lp1;
}

// ---------------- readout ----------------
__global__ void zero_colsum_k() { if (threadIdx.x < CC) g_colsum[threadIdx.x] = 0.f; }

__global__ void reduce_cols_k(const __nv_bfloat16* __restrict__ hh,
                              const __nv_bfloat16* __restrict__ hl) {
    int c = threadIdx.x;
    float acc = 0.f;
    for (int n = blockIdx.x; n < NN; n += gridDim.x) {
        size_t o = (size_t)n * CC + c;
        float v = __bfloat162float(hh[o]) + __bfloat162float(hl[o]);
        acc += (v >= 0.f) ? v : NEG_SLOPE * v;
    }
    atomicAdd(&g_colsum[c], acc);
}

__global__ void finalize_k(const float* __restrict__ wpred, const float* __restrict__ bpred,
                           float* __restrict__ out) {
    int lane = threadIdx.x;
    float s = 0.f;
    for (int c = lane; c < CC; c += 32) s += g_colsum[c] * wpred[c];
    for (int o = 16; o; o >>= 1) s += __shfl_xor_sync(0xFFFFFFFFu, s, o);
    if (lane == 0) out[0] = s * (1.0f / (float)NN) + bpred[0];
}

// ---------------- launch ----------------
extern "C" void kernel_launch(void* const* d_in, const int* in_sizes, int n_in,
                              void* d_out, int out_size) {
    const float* x      = (const float*)d_in[0];
    const void*  edges  = d_in[1];
    const float* W_in   = (const float*)d_in[2];
    const float* W_mpnn = (const float*)d_in[3];
    const float* W_ih   = (const float*)d_in[4];
    const float* W_hh   = (const float*)d_in[5];
    const float* b_ih   = (const float*)d_in[6];
    const float* b_hh   = (const float*)d_in[7];
    const float* W_pred = (const float*)d_in[8];
    const float* b_pred = (const float*)d_in[9];
    float* out = (float*)d_out;

    void *p_hh0, *p_hl0, *p_hh1, *p_hl1, *p_ah, *p_al;
    void *p_xh, *p_xl, *p_Beh, *p_Bel, *p_Bgh, *p_Bgl;
    cudaGetSymbolAddress(&p_hh0, g_hh0); cudaGetSymbolAddress(&p_hl0, g_hl0);
    cudaGetSymbolAddress(&p_hh1, g_hh1); cudaGetSymbolAddress(&p_hl1, g_hl1);
    cudaGetSymbolAddress(&p_ah, g_ah);   cudaGetSymbolAddress(&p_al, g_al);
    cudaGetSymbolAddress(&p_xh, g_xh);   cudaGetSymbolAddress(&p_xl, g_xl);
    cudaGetSymbolAddress(&p_Beh, g_Bemb_h); cudaGetSymbolAddress(&p_Bel, g_Bemb_l);
    cudaGetSymbolAddress(&p_Bgh, g_Bg_h);   cudaGetSymbolAddress(&p_Bgl, g_Bg_l);

    __nv_bfloat16* hhbuf[2] = { (__nv_bfloat16*)p_hh0, (__nv_bfloat16*)p_hh1 };
    __nv_bfloat16* hlbuf[2] = { (__nv_bfloat16*)p_hl0, (__nv_bfloat16*)p_hl1 };
    __nv_bfloat16 *ah = (__nv_bfloat16*)p_ah, *al = (__nv_bfloat16*)p_al;
    __nv_bfloat16 *xh = (__nv_bfloat16*)p_xh, *xl = (__nv_bfloat16*)p_xl;
    __nv_bfloat16 *Beh = (__nv_bfloat16*)p_Beh, *Bel = (__nv_bfloat16*)p_Bel;

    cudaFuncSetAttribute(tc_gemm_embed, cudaFuncAttributeMaxDynamicSharedMemorySize, EMB_SMEM);
    cudaFuncSetAttribute(tc_gemm_gru,   cudaFuncAttributeMaxDynamicSharedMemorySize, GRU_SMEM);

    const int NB = (NN + 1023) / 1024;

    // CSR build
    detect_k<<<1, 32>>>(edges);
    zero_deg_k<<<128, 256>>>();
    hist_k<<<512, 256>>>(edges);
    scan1_k<<<NB, 1024>>>();
    scan2_k<<<1, 32>>>(NB);
    scan3_k<<<NB, 1024>>>();
    scatter_k<<<512, 256>>>(edges);

    // operand prep
    convert_x_k<<<(NN * FIN + 255) / 256, 256>>>(x);
    pack_emb_k<<<(CC * FIN + 255) / 256, 256>>>(W_in);
    for (int s = 0; s < NSTEP; ++s) {
        w1_k<<<(384 * 128 + 255) / 256, 256>>>(W_mpnn + (size_t)s * CC * CC, W_ih, s);
        pack_gru_k<<<(512 * 256 + 255) / 256, 256>>>(W_hh, s);
    }

    dim3 gridE((NN + 127) / 128, 1);
    dim3 gridG((NN + 63) / 64, 1);

    tc_gemm_embed<<<gridE, 256, EMB_SMEM>>>(xh, xl, Beh, Bel,
                                            hhbuf[0], hlbuf[0], NN);

    int cur = 0;
    for (int step = 0; step < NSTEP; ++step) {
        aggregate_k<<<NN / 8, 256>>>(hhbuf[cur], hlbuf[cur]);

        __nv_bfloat16* Bgh = (__nv_bfloat16*)p_Bgh + (size_t)step * 512 * 256;
        __nv_bfloat16* Bgl = (__nv_bfloat16*)p_Bgl + (size_t)step * 512 * 256;
        tc_gemm_gru<<<gridG, 256, GRU_SMEM>>>(ah, al, hhbuf[cur], hlbuf[cur],
                                              Bgh, Bgl,
                                              hhbuf[1 - cur], hlbuf[1 - cur],
                                              b_ih, b_hh, NN);
        cur = 1 - cur;
    }

    zero_colsum_k<<<1, 128>>>();
    reduce_cols_k<<<2048, 128>>>(hhbuf[cur], hlbuf[cur]);
    finalize_k<<<1, 32>>>(W_pred, b_pred, out);
}